// round 1
// baseline (speedup 1.0000x reference)
#include <cuda_runtime.h>
#include <cstdint>

// ---------------------------------------------------------------------------
// RelationalFeatureExtractor:
//   out[b,h,i,j] = (silu(feat(q[b,i],k[b,j]) @ W1 + b1) @ W2 + b2)[h]
// feat = 64 fourier features of pairwise geometry.
// One CTA per (b,i); thread j handles key j. GEMM1/GEMM2 via packed
// fma.rn.f32x2 with W1/W2/b1/b2 staged in shared memory.
// ---------------------------------------------------------------------------

#define NTHREADS 256

// shared layout (in floats)
#define W1_OFF 0          // 16384 floats (64 x 256, f-major)
#define W2_OFF 16384      // 2048 floats (256 x 8)
#define B1_OFF 18432      // 256
#define B2_OFF 18688      // 8
#define Q_OFF  18696      // 12 (10 used)
#define K_OFF  18708      // 256 * 11 (stride 11 -> conflict free)
#define SMEM_FLOATS (K_OFF + 256 * 11)
#define SMEM_BYTES (SMEM_FLOATS * 4)

__device__ __forceinline__ unsigned long long pack2(float lo, float hi) {
    unsigned long long r;
    asm("mov.b64 %0, {%1, %2};" : "=l"(r) : "f"(lo), "f"(hi));
    return r;
}
__device__ __forceinline__ void unpack2(unsigned long long v, float& lo, float& hi) {
    asm("mov.b64 {%0, %1}, %2;" : "=f"(lo), "=f"(hi) : "l"(v));
}
__device__ __forceinline__ unsigned long long ffma2(unsigned long long a,
                                                    unsigned long long b,
                                                    unsigned long long c) {
    unsigned long long d;
    asm("fma.rn.f32x2 %0, %1, %2, %3;" : "=l"(d) : "l"(a), "l"(b), "l"(c));
    return d;
}

__device__ __forceinline__ float silu_f(float x) {
    // x * sigmoid(x), fp32; __expf/__fdividef ~1e-7 rel err
    float e = __expf(-x);
    return x * __fdividef(1.0f, 1.0f + e);
}

__global__ void __launch_bounds__(NTHREADS, 1)
relfeat_kernel(const float* __restrict__ Q,   // (8,256,10)
               const float* __restrict__ K,   // (8,256,10)
               const float* __restrict__ W1,  // (64,256)
               const float* __restrict__ b1,  // (256)
               const float* __restrict__ W2,  // (256,8)
               const float* __restrict__ b2,  // (8)
               float* __restrict__ out)       // (8,8,256,256)
{
    extern __shared__ float sm[];
    const int t = threadIdx.x;
    const int i = blockIdx.x;   // query index 0..255
    const int b = blockIdx.y;   // batch 0..7

    // ---- stage weights / rows into shared ----
    {
        float4* w1d = reinterpret_cast<float4*>(sm + W1_OFF);
        const float4* w1s = reinterpret_cast<const float4*>(W1);
        #pragma unroll
        for (int idx = t; idx < 16384 / 4; idx += NTHREADS) w1d[idx] = w1s[idx];

        float4* w2d = reinterpret_cast<float4*>(sm + W2_OFF);
        const float4* w2s = reinterpret_cast<const float4*>(W2);
        #pragma unroll
        for (int idx = t; idx < 2048 / 4; idx += NTHREADS) w2d[idx] = w2s[idx];

        if (t < 64) reinterpret_cast<float4*>(sm + B1_OFF)[t] =
                        reinterpret_cast<const float4*>(b1)[t];
        if (t < 8)  sm[B2_OFF + t] = b2[t];
        if (t < 10) sm[Q_OFF + t] = Q[((size_t)b * 256 + i) * 10 + t];

        // key rows, padded stride 11
        const float* kr = K + ((size_t)b * 256 + t) * 10;
        #pragma unroll
        for (int c = 0; c < 10; ++c) sm[K_OFF + t * 11 + c] = kr[c];
    }
    __syncthreads();

    // ---- per-thread feature computation (j = t) ----
    const float qteam = sm[Q_OFF + 0];
    const float qpx = sm[Q_OFF + 3], qpy = sm[Q_OFF + 4];
    const float qvx = sm[Q_OFF + 5], qvy = sm[Q_OFF + 6];
    const float qax = sm[Q_OFF + 7], qay = sm[Q_OFF + 8];

    const float* kr = sm + K_OFF + t * 11;
    const float kteam = kr[0];
    const float kpx = kr[3], kpy = kr[4];
    const float kvx = kr[5], kvy = kr[6];
    const float kax = kr[7], kay = kr[8];

    const float dpx = kpx - qpx, dpy = kpy - qpy;
    const float dvx = kvx - qvx, dvy = kvy - qvy;

    const float dist_sq = dpx * dpx + dpy * dpy;
    const float dist = sqrtf(dist_sq + 1e-6f);
    const float inv_dist = 1.0f / (dist + 0.1f);
    const float binv = 1.0f / (dist + 1e-6f);
    const float bx = dpx * binv, by = dpy * binv;
    const float ata = bx * qax + by * qay;
    const float aspect = bx * kax + by * kay;
    const float dot_dp_dv = dpx * dvx + dpy * dvy;
    const float speed_sq = dvx * dvx + dvy * dvy;
    const float ttca_arg = fmaxf(-dot_dp_dv / (speed_sq + 1e-6f), 0.0f);
    const float ttca = tanhf(ttca_arg);
    const float same_team = (qteam == kteam) ? 1.0f : 0.0f;
    const float q_speed = sqrtf(qvx * qvx + qvy * qvy);
    const float k_speed = sqrtf(kvx * kvx + kvy * kvy);
    const float delta_speed = k_speed - q_speed;

    // 64 features, each duplicated into both halves of a 64-bit reg.
    unsigned long long feat2[64];
    {
        // fourier(v, nf): per dim layout = [sin(v*2^0..2^{nf-1}), cos(...)]
        const float in4[4] = { dist, inv_dist, ata, aspect };
        #pragma unroll
        for (int d = 0; d < 4; ++d) {
            #pragma unroll
            for (int kk = 0; kk < 4; ++kk) {
                float s, c;
                __sincosf(in4[d] * (float)(1 << kk), &s, &c);
                feat2[d * 8 + kk]     = pack2(s, s);
                feat2[d * 8 + 4 + kk] = pack2(c, c);
            }
        }
        const float in2[8] = { dpx, dpy, dvx, dvy, ttca, dist, same_team, delta_speed };
        #pragma unroll
        for (int d = 0; d < 8; ++d) {
            #pragma unroll
            for (int kk = 0; kk < 2; ++kk) {
                float s, c;
                __sincosf(in2[d] * (float)(1 << kk), &s, &c);
                feat2[32 + d * 4 + kk]     = pack2(s, s);
                feat2[32 + d * 4 + 2 + kk] = pack2(c, c);
            }
        }
    }

    // ---- fused GEMM1 + silu + GEMM2 ----
    unsigned long long o0 = pack2(sm[B2_OFF + 0], sm[B2_OFF + 1]);
    unsigned long long o1 = pack2(sm[B2_OFF + 2], sm[B2_OFF + 3]);
    unsigned long long o2 = pack2(sm[B2_OFF + 4], sm[B2_OFF + 5]);
    unsigned long long o3 = pack2(sm[B2_OFF + 6], sm[B2_OFF + 7]);

    #pragma unroll 1
    for (int uq = 0; uq < 64; ++uq) {          // 4 hidden units per iter
        const float* col = sm + W1_OFF + uq * 4;
        const ulonglong2 bi =
            *reinterpret_cast<const ulonglong2*>(sm + B1_OFF + uq * 4);
        unsigned long long a0 = bi.x;          // (u, u+1) accumulators
        unsigned long long a1 = bi.y;          // (u+2, u+3)
        #pragma unroll
        for (int f = 0; f < 64; ++f) {
            const ulonglong2 w =
                *reinterpret_cast<const ulonglong2*>(col + f * 256);
            a0 = ffma2(feat2[f], w.x, a0);
            a1 = ffma2(feat2[f], w.y, a1);
        }
        float x0, x1, x2, x3;
        unpack2(a0, x0, x1);
        unpack2(a1, x2, x3);
        float hs[4];
        hs[0] = silu_f(x0); hs[1] = silu_f(x1);
        hs[2] = silu_f(x2); hs[3] = silu_f(x3);

        const float* w2r = sm + W2_OFF + uq * 32;  // 4 rows of 8
        #pragma unroll
        for (int s = 0; s < 4; ++s) {
            const unsigned long long hh = pack2(hs[s], hs[s]);
            const ulonglong2 wa =
                *reinterpret_cast<const ulonglong2*>(w2r + s * 8);
            const ulonglong2 wb =
                *reinterpret_cast<const ulonglong2*>(w2r + s * 8 + 4);
            o0 = ffma2(hh, wa.x, o0);
            o1 = ffma2(hh, wa.y, o1);
            o2 = ffma2(hh, wb.x, o2);
            o3 = ffma2(hh, wb.y, o3);
        }
    }

    // ---- write out[b][h][i][j], coalesced over j ----
    float r[8];
    unpack2(o0, r[0], r[1]);
    unpack2(o1, r[2], r[3]);
    unpack2(o2, r[4], r[5]);
    unpack2(o3, r[6], r[7]);
    const size_t base = (((size_t)b * 8) * 256 + i) * 256 + t;
    #pragma unroll
    for (int h = 0; h < 8; ++h)
        out[base + (size_t)h * 65536] = r[h];
}

extern "C" void kernel_launch(void* const* d_in, const int* in_sizes, int n_in,
                              void* d_out, int out_size) {
    const float* Q  = (const float*)d_in[0];
    const float* K  = (const float*)d_in[1];
    const float* W1 = (const float*)d_in[2];
    const float* b1 = (const float*)d_in[3];
    const float* W2 = (const float*)d_in[4];
    const float* b2 = (const float*)d_in[5];
    float* out = (float*)d_out;

    cudaFuncSetAttribute(relfeat_kernel,
                         cudaFuncAttributeMaxDynamicSharedMemorySize,
                         SMEM_BYTES);
    dim3 grid(256, 8);
    relfeat_kernel<<<grid, NTHREADS, SMEM_BYTES>>>(Q, K, W1, b1, W2, b2, out);
}

// round 2
// speedup vs baseline: 1.0005x; 1.0005x over previous
#include <cuda_runtime.h>
#include <cstdint>

// ---------------------------------------------------------------------------
// RelationalFeatureExtractor:
//   out[b,h,i,j] = (silu(feat(q[b,i],k[b,j]) @ W1 + b1) @ W2 + b2)[h]
// feat = 64 fourier features of pairwise geometry.
// One CTA per (b,i); thread j handles key j. GEMM1/GEMM2 via packed
// fma.rn.f32x2 with W1/W2/b1/b2 staged in shared memory.
// ---------------------------------------------------------------------------

#define NTHREADS 256

// shared layout (in floats)
#define W1_OFF 0          // 16384 floats (64 x 256, f-major)
#define W2_OFF 16384      // 2048 floats (256 x 8)
#define B1_OFF 18432      // 256
#define B2_OFF 18688      // 8
#define Q_OFF  18696      // 12 (10 used)
#define K_OFF  18708      // 256 * 11 (stride 11 -> conflict free)
#define SMEM_FLOATS (K_OFF + 256 * 11)
#define SMEM_BYTES (SMEM_FLOATS * 4)

__device__ __forceinline__ unsigned long long pack2(float lo, float hi) {
    unsigned long long r;
    asm("mov.b64 %0, {%1, %2};" : "=l"(r) : "f"(lo), "f"(hi));
    return r;
}
__device__ __forceinline__ void unpack2(unsigned long long v, float& lo, float& hi) {
    asm("mov.b64 {%0, %1}, %2;" : "=f"(lo), "=f"(hi) : "l"(v));
}
__device__ __forceinline__ unsigned long long ffma2(unsigned long long a,
                                                    unsigned long long b,
                                                    unsigned long long c) {
    unsigned long long d;
    asm("fma.rn.f32x2 %0, %1, %2, %3;" : "=l"(d) : "l"(a), "l"(b), "l"(c));
    return d;
}

__device__ __forceinline__ float silu_f(float x) {
    // x * sigmoid(x), fp32; __expf/__fdividef ~1e-7 rel err
    float e = __expf(-x);
    return x * __fdividef(1.0f, 1.0f + e);
}

__global__ void __launch_bounds__(NTHREADS, 1)
relfeat_kernel(const float* __restrict__ Q,   // (8,256,10)
               const float* __restrict__ K,   // (8,256,10)
               const float* __restrict__ W1,  // (64,256)
               const float* __restrict__ b1,  // (256)
               const float* __restrict__ W2,  // (256,8)
               const float* __restrict__ b2,  // (8)
               float* __restrict__ out)       // (8,8,256,256)
{
    extern __shared__ float sm[];
    const int t = threadIdx.x;
    const int i = blockIdx.x;   // query index 0..255
    const int b = blockIdx.y;   // batch 0..7

    // ---- stage weights / rows into shared ----
    {
        float4* w1d = reinterpret_cast<float4*>(sm + W1_OFF);
        const float4* w1s = reinterpret_cast<const float4*>(W1);
        #pragma unroll
        for (int idx = t; idx < 16384 / 4; idx += NTHREADS) w1d[idx] = w1s[idx];

        float4* w2d = reinterpret_cast<float4*>(sm + W2_OFF);
        const float4* w2s = reinterpret_cast<const float4*>(W2);
        #pragma unroll
        for (int idx = t; idx < 2048 / 4; idx += NTHREADS) w2d[idx] = w2s[idx];

        if (t < 64) reinterpret_cast<float4*>(sm + B1_OFF)[t] =
                        reinterpret_cast<const float4*>(b1)[t];
        if (t < 8)  sm[B2_OFF + t] = b2[t];
        if (t < 10) sm[Q_OFF + t] = Q[((size_t)b * 256 + i) * 10 + t];

        // key rows, padded stride 11
        const float* kr = K + ((size_t)b * 256 + t) * 10;
        #pragma unroll
        for (int c = 0; c < 10; ++c) sm[K_OFF + t * 11 + c] = kr[c];
    }
    __syncthreads();

    // ---- per-thread feature computation (j = t) ----
    const float qteam = sm[Q_OFF + 0];
    const float qpx = sm[Q_OFF + 3], qpy = sm[Q_OFF + 4];
    const float qvx = sm[Q_OFF + 5], qvy = sm[Q_OFF + 6];
    const float qax = sm[Q_OFF + 7], qay = sm[Q_OFF + 8];

    const float* kr = sm + K_OFF + t * 11;
    const float kteam = kr[0];
    const float kpx = kr[3], kpy = kr[4];
    const float kvx = kr[5], kvy = kr[6];
    const float kax = kr[7], kay = kr[8];

    const float dpx = kpx - qpx, dpy = kpy - qpy;
    const float dvx = kvx - qvx, dvy = kvy - qvy;

    const float dist_sq = dpx * dpx + dpy * dpy;
    const float dist = sqrtf(dist_sq + 1e-6f);
    const float inv_dist = 1.0f / (dist + 0.1f);
    const float binv = 1.0f / (dist + 1e-6f);
    const float bx = dpx * binv, by = dpy * binv;
    const float ata = bx * qax + by * qay;
    const float aspect = bx * kax + by * kay;
    const float dot_dp_dv = dpx * dvx + dpy * dvy;
    const float speed_sq = dvx * dvx + dvy * dvy;
    const float ttca_arg = fmaxf(-dot_dp_dv / (speed_sq + 1e-6f), 0.0f);
    const float ttca = tanhf(ttca_arg);
    const float same_team = (qteam == kteam) ? 1.0f : 0.0f;
    const float q_speed = sqrtf(qvx * qvx + qvy * qvy);
    const float k_speed = sqrtf(kvx * kvx + kvy * kvy);
    const float delta_speed = k_speed - q_speed;

    // 64 features, each duplicated into both halves of a 64-bit reg.
    unsigned long long feat2[64];
    {
        // fourier(v, nf): per dim layout = [sin(v*2^0..2^{nf-1}), cos(...)]
        const float in4[4] = { dist, inv_dist, ata, aspect };
        #pragma unroll
        for (int d = 0; d < 4; ++d) {
            #pragma unroll
            for (int kk = 0; kk < 4; ++kk) {
                float s, c;
                __sincosf(in4[d] * (float)(1 << kk), &s, &c);
                feat2[d * 8 + kk]     = pack2(s, s);
                feat2[d * 8 + 4 + kk] = pack2(c, c);
            }
        }
        const float in2[8] = { dpx, dpy, dvx, dvy, ttca, dist, same_team, delta_speed };
        #pragma unroll
        for (int d = 0; d < 8; ++d) {
            #pragma unroll
            for (int kk = 0; kk < 2; ++kk) {
                float s, c;
                __sincosf(in2[d] * (float)(1 << kk), &s, &c);
                feat2[32 + d * 4 + kk]     = pack2(s, s);
                feat2[32 + d * 4 + 2 + kk] = pack2(c, c);
            }
        }
    }

    // ---- fused GEMM1 + silu + GEMM2 ----
    unsigned long long o0 = pack2(sm[B2_OFF + 0], sm[B2_OFF + 1]);
    unsigned long long o1 = pack2(sm[B2_OFF + 2], sm[B2_OFF + 3]);
    unsigned long long o2 = pack2(sm[B2_OFF + 4], sm[B2_OFF + 5]);
    unsigned long long o3 = pack2(sm[B2_OFF + 6], sm[B2_OFF + 7]);

    #pragma unroll 1
    for (int uq = 0; uq < 64; ++uq) {          // 4 hidden units per iter
        const float* col = sm + W1_OFF + uq * 4;
        const ulonglong2 bi =
            *reinterpret_cast<const ulonglong2*>(sm + B1_OFF + uq * 4);
        unsigned long long a0 = bi.x;          // (u, u+1) accumulators
        unsigned long long a1 = bi.y;          // (u+2, u+3)
        #pragma unroll
        for (int f = 0; f < 64; ++f) {
            const ulonglong2 w =
                *reinterpret_cast<const ulonglong2*>(col + f * 256);
            a0 = ffma2(feat2[f], w.x, a0);
            a1 = ffma2(feat2[f], w.y, a1);
        }
        float x0, x1, x2, x3;
        unpack2(a0, x0, x1);
        unpack2(a1, x2, x3);
        float hs[4];
        hs[0] = silu_f(x0); hs[1] = silu_f(x1);
        hs[2] = silu_f(x2); hs[3] = silu_f(x3);

        const float* w2r = sm + W2_OFF + uq * 32;  // 4 rows of 8
        #pragma unroll
        for (int s = 0; s < 4; ++s) {
            const unsigned long long hh = pack2(hs[s], hs[s]);
            const ulonglong2 wa =
                *reinterpret_cast<const ulonglong2*>(w2r + s * 8);
            const ulonglong2 wb =
                *reinterpret_cast<const ulonglong2*>(w2r + s * 8 + 4);
            o0 = ffma2(hh, wa.x, o0);
            o1 = ffma2(hh, wa.y, o1);
            o2 = ffma2(hh, wb.x, o2);
            o3 = ffma2(hh, wb.y, o3);
        }
    }

    // ---- write out[b][h][i][j], coalesced over j ----
    float r[8];
    unpack2(o0, r[0], r[1]);
    unpack2(o1, r[2], r[3]);
    unpack2(o2, r[4], r[5]);
    unpack2(o3, r[6], r[7]);
    const size_t base = (((size_t)b * 8) * 256 + i) * 256 + t;
    #pragma unroll
    for (int h = 0; h < 8; ++h)
        out[base + (size_t)h * 65536] = r[h];
}

extern "C" void kernel_launch(void* const* d_in, const int* in_sizes, int n_in,
                              void* d_out, int out_size) {
    const float* Q  = (const float*)d_in[0];
    const float* K  = (const float*)d_in[1];
    const float* W1 = (const float*)d_in[2];
    const float* b1 = (const float*)d_in[3];
    const float* W2 = (const float*)d_in[4];
    const float* b2 = (const float*)d_in[5];
    float* out = (float*)d_out;

    cudaFuncSetAttribute(relfeat_kernel,
                         cudaFuncAttributeMaxDynamicSharedMemorySize,
                         SMEM_BYTES);
    dim3 grid(256, 8);
    relfeat_kernel<<<grid, NTHREADS, SMEM_BYTES>>>(Q, K, W1, b1, W2, b2, out);
}

// round 5
// speedup vs baseline: 1.7453x; 1.7443x over previous
#include <cuda_runtime.h>
#include <cuda_bf16.h>
#include <cstdint>

#define THREADS 256

// prep-built W1^T bf16 image: [n=256][k=72 pad], hi @0, lo @36864
__device__ __align__(16) uint8_t g_B1[73728];

// smem byte offsets
#define A_HI_OFF   0        // feat hi [256][72 bf16] = 36864
#define A_LO_OFF   36864    // feat lo
#define HBUF_OFF   0        // f32 [256][68] = 69632, aliases A region (dead after frag loads)
#define B1H_OFF    73728
#define B1L_OFF    110592
#define W2F_OFF    147456   // f32 [256][8] = 8192
#define B1V_OFF    155648   // 256 f32
#define B2V_OFF    156672   // 8 f32
#define SMEM_BYTES 156704

#define LDMX4(r, a) asm volatile( \
    "ldmatrix.sync.aligned.m8n8.x4.shared.b16 {%0,%1,%2,%3}, [%4];" \
    : "=r"((r)[0]), "=r"((r)[1]), "=r"((r)[2]), "=r"((r)[3]) : "r"(a))
#define LDMX2(r0, r1, a) asm volatile( \
    "ldmatrix.sync.aligned.m8n8.x2.shared.b16 {%0,%1}, [%2];" \
    : "=r"(r0), "=r"(r1) : "r"(a))

static __device__ __forceinline__ uint32_t smem_u32(const void* p) {
    uint32_t a;
    asm("{ .reg .u64 t; cvta.to.shared.u64 t, %1; cvt.u32.u64 %0, t; }" : "=r"(a) : "l"(p));
    return a;
}
static __device__ __forceinline__ void mma16816(float* c, const uint32_t* a,
                                                uint32_t b0, uint32_t b1) {
    asm("mma.sync.aligned.m16n8k16.row.col.f32.bf16.bf16.f32 "
        "{%0,%1,%2,%3}, {%4,%5,%6,%7}, {%8,%9}, {%0,%1,%2,%3};"
        : "+f"(c[0]), "+f"(c[1]), "+f"(c[2]), "+f"(c[3])
        : "r"(a[0]), "r"(a[1]), "r"(a[2]), "r"(a[3]), "r"(b0), "r"(b1));
}
static __device__ __forceinline__ unsigned long long pack2(float lo, float hi) {
    unsigned long long r;
    asm("mov.b64 %0, {%1, %2};" : "=l"(r) : "f"(lo), "f"(hi));
    return r;
}
static __device__ __forceinline__ void unpack2(unsigned long long v, float& lo, float& hi) {
    asm("mov.b64 {%0, %1}, %2;" : "=f"(lo), "=f"(hi) : "l"(v));
}
static __device__ __forceinline__ unsigned long long ffma2(unsigned long long a,
                                                           unsigned long long b,
                                                           unsigned long long c) {
    unsigned long long d;
    asm("fma.rn.f32x2 %0, %1, %2, %3;" : "=l"(d) : "l"(a), "l"(b), "l"(c));
    return d;
}
static __device__ __forceinline__ void split2(float a, float b, uint32_t& hi, uint32_t& lo) {
    __nv_bfloat16 ha = __float2bfloat16(a), hb = __float2bfloat16(b);
    __nv_bfloat16 la = __float2bfloat16(a - __bfloat162float(ha));
    __nv_bfloat16 lb = __float2bfloat16(b - __bfloat162float(hb));
    hi = (uint32_t)*(uint16_t*)&ha | ((uint32_t)*(uint16_t*)&hb << 16);
    lo = (uint32_t)*(uint16_t*)&la | ((uint32_t)*(uint16_t*)&lb << 16);
}
static __device__ __forceinline__ float silu_f(float x) {
    float e = __expf(-x);
    return x * __fdividef(1.0f, 1.0f + e);
}

__global__ void prep_kernel(const float* __restrict__ W1) {
    int t0 = blockIdx.x * blockDim.x + threadIdx.x;
    int stride = gridDim.x * blockDim.x;
    uint16_t* b1h = (uint16_t*)g_B1;
    uint16_t* b1l = (uint16_t*)(g_B1 + 36864);
    for (int idx = t0; idx < 64 * 256; idx += stride) {
        int k = idx >> 8, n = idx & 255;          // W1 is (64, 256): W1[k][n]
        float v = W1[idx];
        __nv_bfloat16 h = __float2bfloat16(v);
        __nv_bfloat16 l = __float2bfloat16(v - __bfloat162float(h));
        b1h[n * 72 + k] = *(uint16_t*)&h;
        b1l[n * 72 + k] = *(uint16_t*)&l;
    }
}

__global__ void __launch_bounds__(THREADS, 1)
relfeat_mma(const float* __restrict__ Q, const float* __restrict__ K,
            const float* __restrict__ b1, const float* __restrict__ W2,
            const float* __restrict__ b2, float* __restrict__ out) {
    extern __shared__ char sm[];
    const uint32_t smb = smem_u32(sm);
    const int t = threadIdx.x;
    const int w = t >> 5, lane = t & 31;
    const int g = lane >> 2, tq = lane & 3;
    const int i = blockIdx.x & 255, b = blockIdx.x >> 8;

    // ---- stage weights ----
    {
        const uint4* s1 = (const uint4*)g_B1;
        uint4* d1 = (uint4*)(sm + B1H_OFF);
        for (int idx = t; idx < 4608; idx += THREADS) d1[idx] = s1[idx];
        if (t < 512 - 256) {}  // (no-op, keep simple)
        float4* w2d = (float4*)(sm + W2F_OFF);
        const float4* w2s = (const float4*)W2;
        for (int idx = t; idx < 512; idx += THREADS) w2d[idx] = w2s[idx];
        ((float*)(sm + B1V_OFF))[t] = b1[t];
        if (t < 8) ((float*)(sm + B2V_OFF))[t] = b2[t];
    }

    // ---- features for row j = t ----
    {
        const float* qr = Q + ((size_t)b * 256 + i) * 10;
        const float* kr = K + ((size_t)b * 256 + t) * 10;
        float qteam = qr[0], qpx = qr[3], qpy = qr[4], qvx = qr[5], qvy = qr[6],
              qax = qr[7], qay = qr[8];
        float kteam = kr[0], kpx = kr[3], kpy = kr[4], kvx = kr[5], kvy = kr[6],
              kax = kr[7], kay = kr[8];
        float dpx = kpx - qpx, dpy = kpy - qpy;
        float dvx = kvx - qvx, dvy = kvy - qvy;
        float dist = sqrtf(dpx * dpx + dpy * dpy + 1e-6f);
        float inv_dist = 1.0f / (dist + 0.1f);
        float binv = 1.0f / (dist + 1e-6f);
        float bx = dpx * binv, by = dpy * binv;
        float ata = bx * qax + by * qay;
        float aspect = bx * kax + by * kay;
        float dot = dpx * dvx + dpy * dvy;
        float ss = dvx * dvx + dvy * dvy;
        float ttca = tanhf(fmaxf(-dot / (ss + 1e-6f), 0.0f));
        float same = (qteam == kteam) ? 1.0f : 0.0f;
        float dspd = sqrtf(kvx * kvx + kvy * kvy) - sqrtf(qvx * qvx + qvy * qvy);

        float f[64];
        const float in4[4] = { dist, inv_dist, ata, aspect };
        #pragma unroll
        for (int d = 0; d < 4; ++d)
            #pragma unroll
            for (int kk = 0; kk < 4; ++kk) {
                float s, c;
                __sincosf(in4[d] * (float)(1 << kk), &s, &c);
                f[d * 8 + kk] = s; f[d * 8 + 4 + kk] = c;
            }
        const float in2[8] = { dpx, dpy, dvx, dvy, ttca, dist, same, dspd };
        #pragma unroll
        for (int d = 0; d < 8; ++d)
            #pragma unroll
            for (int kk = 0; kk < 2; ++kk) {
                float s, c;
                __sincosf(in2[d] * (float)(1 << kk), &s, &c);
                f[32 + d * 4 + kk] = s; f[32 + d * 4 + 2 + kk] = c;
            }

        uint32_t hw[32], lw[32];
        #pragma unroll
        for (int e = 0; e < 32; ++e) split2(f[2 * e], f[2 * e + 1], hw[e], lw[e]);
        uint4* rowh = (uint4*)(sm + A_HI_OFF + t * 144);
        uint4* rowl = (uint4*)(sm + A_LO_OFF + t * 144);
        #pragma unroll
        for (int q = 0; q < 8; ++q) {
            rowh[q] = make_uint4(hw[4 * q], hw[4 * q + 1], hw[4 * q + 2], hw[4 * q + 3]);
            rowl[q] = make_uint4(lw[4 * q], lw[4 * q + 1], lw[4 * q + 2], lw[4 * q + 3]);
        }
    }
    __syncthreads();

    // ---- A fragments via ldmatrix (hardware-canonical layout) ----
    uint32_t ah[2][4][4], al[2][4][4];
    #pragma unroll
    for (int mt = 0; mt < 2; ++mt)
        #pragma unroll
        for (int s = 0; s < 4; ++s) {
            uint32_t row = (uint32_t)(w * 32 + mt * 16 + (lane & 15));
            uint32_t addr = smb + A_HI_OFF + row * 144 + 32 * s + ((lane >> 4) & 1) * 16;
            LDMX4(ah[mt][s], addr);
            LDMX4(al[mt][s], addr + 36864);
        }

    const float* b1v = (const float*)(sm + B1V_OFF);
    const float* b2v = (const float*)(sm + B2V_OFF);
    float* hb = (float*)(sm + HBUF_OFF);

    // output accumulators (f32x2 pairs over 8 heads)
    unsigned long long o0 = pack2(b2v[0], b2v[1]);
    unsigned long long o1 = pack2(b2v[2], b2v[3]);
    unsigned long long o2 = pack2(b2v[4], b2v[5]);
    unsigned long long o3 = pack2(b2v[6], b2v[7]);

    #pragma unroll 1
    for (int cch = 0; cch < 4; ++cch) {
        // ---- GEMM1 (mma, bf16 hi/lo 3-chain): D1 chunk [256 j][64 n] ----
        float acc[2][8][4];
        #pragma unroll
        for (int mt = 0; mt < 2; ++mt)
            #pragma unroll
            for (int nt = 0; nt < 8; ++nt) {
                const int n0 = cch * 64 + nt * 8 + 2 * tq;
                acc[mt][nt][0] = b1v[n0];     acc[mt][nt][1] = b1v[n0 + 1];
                acc[mt][nt][2] = b1v[n0];     acc[mt][nt][3] = b1v[n0 + 1];
            }
        #pragma unroll
        for (int s = 0; s < 4; ++s)
            #pragma unroll
            for (int nt = 0; nt < 8; ++nt) {
                uint32_t brow = (uint32_t)(cch * 64 + nt * 8 + (lane & 7));
                uint32_t baddr = smb + B1H_OFF + brow * 144 + 32 * s +
                                 ((lane >> 3) & 1) * 16;
                uint32_t bh0, bh1, bl0, bl1;
                LDMX2(bh0, bh1, baddr);
                LDMX2(bl0, bl1, baddr + 36864);
                #pragma unroll
                for (int mt = 0; mt < 2; ++mt) {
                    mma16816(acc[mt][nt], ah[mt][s], bh0, bh1);
                    mma16816(acc[mt][nt], ah[mt][s], bl0, bl1);
                    mma16816(acc[mt][nt], al[mt][s], bh0, bh1);
                }
            }
        __syncthreads();   // protect HBUF (prev chunk reads / A region frag loads done)
        // ---- silu -> HBUF (f32 [256][68]) ----
        #pragma unroll
        for (int mt = 0; mt < 2; ++mt) {
            const int r = w * 32 + mt * 16 + g;
            #pragma unroll
            for (int nt = 0; nt < 8; ++nt) {
                const int c2 = nt * 8 + 2 * tq;
                hb[r * 68 + c2]           = silu_f(acc[mt][nt][0]);
                hb[r * 68 + c2 + 1]       = silu_f(acc[mt][nt][1]);
                hb[(r + 8) * 68 + c2]     = silu_f(acc[mt][nt][2]);
                hb[(r + 8) * 68 + c2 + 1] = silu_f(acc[mt][nt][3]);
            }
        }
        __syncthreads();
        // ---- GEMM2 (scalar f32x2): o[8] += H[t][k] * W2[k][:] ----
        const float4* hrow = (const float4*)(hb + t * 68);
        const ulonglong2* w2p =
            (const ulonglong2*)((const float*)(sm + W2F_OFF) + cch * 64 * 8);
        #pragma unroll
        for (int kk = 0; kk < 16; ++kk) {
            const float4 hv = hrow[kk];
            const float he[4] = { hv.x, hv.y, hv.z, hv.w };
            #pragma unroll
            for (int e = 0; e < 4; ++e) {
                const int k = 4 * kk + e;
                const unsigned long long hh = pack2(he[e], he[e]);
                const ulonglong2 wa = w2p[2 * k];
                const ulonglong2 wb = w2p[2 * k + 1];
                o0 = ffma2(hh, wa.x, o0);
                o1 = ffma2(hh, wa.y, o1);
                o2 = ffma2(hh, wb.x, o2);
                o3 = ffma2(hh, wb.y, o3);
            }
        }
    }

    // ---- store out[b,h,i,j=t], coalesced over t ----
    float r[8];
    unpack2(o0, r[0], r[1]);
    unpack2(o1, r[2], r[3]);
    unpack2(o2, r[4], r[5]);
    unpack2(o3, r[6], r[7]);
    const size_t base = (((size_t)b * 8) * 256 + i) * 256 + t;
    #pragma unroll
    for (int h = 0; h < 8; ++h)
        out[base + (size_t)h * 65536] = r[h];
}

extern "C" void kernel_launch(void* const* d_in, const int* in_sizes, int n_in,
                              void* d_out, int out_size) {
    const float* Q  = (const float*)d_in[0];
    const float* K  = (const float*)d_in[1];
    const float* W1 = (const float*)d_in[2];
    const float* b1 = (const float*)d_in[3];
    const float* W2 = (const float*)d_in[4];
    const float* b2 = (const float*)d_in[5];
    float* out = (float*)d_out;

    prep_kernel<<<16, THREADS>>>(W1);
    cudaFuncSetAttribute(relfeat_mma, cudaFuncAttributeMaxDynamicSharedMemorySize,
                         SMEM_BYTES);
    relfeat_mma<<<2048, THREADS, SMEM_BYTES>>>(Q, K, b1, W2, b2, out);
}

// round 6
// speedup vs baseline: 2.1521x; 1.2331x over previous
#include <cuda_runtime.h>
#include <cuda_bf16.h>
#include <cstdint>

#define THREADS 256

// prep-built W1^T bf16 image, XOR-swizzled rows of 128B: hi @0, lo @32768
__device__ __align__(16) uint8_t g_B1[65536];

// smem byte offsets
#define A_HI_OFF   0        // feat hi [128][72 bf16] = 18432
#define A_LO_OFF   18432
#define HBUF_OFF   0        // f32 [128][68] = 34816, aliases A region
#define B1H_OFF    36864    // 32768 (swizzled, stride 128B)
#define B1L_OFF    69632    // 32768 ; PBUF [128][8]f32 aliases this at end
#define PBUF_OFF   69632
#define W2F_OFF    102400   // f32 [256][8] = 8192
#define B1V_OFF    110592   // 256 f32
#define B2V_OFF    111616   // 8 f32
#define SMEM_BYTES 111648

#define LDMX4(r, a) asm volatile( \
    "ldmatrix.sync.aligned.m8n8.x4.shared.b16 {%0,%1,%2,%3}, [%4];" \
    : "=r"((r)[0]), "=r"((r)[1]), "=r"((r)[2]), "=r"((r)[3]) : "r"(a))
#define LDMX2(r0, r1, a) asm volatile( \
    "ldmatrix.sync.aligned.m8n8.x2.shared.b16 {%0,%1}, [%2];" \
    : "=r"(r0), "=r"(r1) : "r"(a))

static __device__ __forceinline__ uint32_t smem_u32(const void* p) {
    uint32_t a;
    asm("{ .reg .u64 t; cvta.to.shared.u64 t, %1; cvt.u32.u64 %0, t; }" : "=r"(a) : "l"(p));
    return a;
}
static __device__ __forceinline__ void mma16816(float* c, const uint32_t* a,
                                                uint32_t b0, uint32_t b1) {
    asm("mma.sync.aligned.m16n8k16.row.col.f32.bf16.bf16.f32 "
        "{%0,%1,%2,%3}, {%4,%5,%6,%7}, {%8,%9}, {%0,%1,%2,%3};"
        : "+f"(c[0]), "+f"(c[1]), "+f"(c[2]), "+f"(c[3])
        : "r"(a[0]), "r"(a[1]), "r"(a[2]), "r"(a[3]), "r"(b0), "r"(b1));
}
static __device__ __forceinline__ unsigned long long pack2(float lo, float hi) {
    unsigned long long r;
    asm("mov.b64 %0, {%1, %2};" : "=l"(r) : "f"(lo), "f"(hi));
    return r;
}
static __device__ __forceinline__ void unpack2(unsigned long long v, float& lo, float& hi) {
    asm("mov.b64 {%0, %1}, %2;" : "=f"(lo), "=f"(hi) : "l"(v));
}
static __device__ __forceinline__ unsigned long long ffma2(unsigned long long a,
                                                           unsigned long long b,
                                                           unsigned long long c) {
    unsigned long long d;
    asm("fma.rn.f32x2 %0, %1, %2, %3;" : "=l"(d) : "l"(a), "l"(b), "l"(c));
    return d;
}
static __device__ __forceinline__ void split2(float a, float b, uint32_t& hi, uint32_t& lo) {
    __nv_bfloat16 ha = __float2bfloat16(a), hb = __float2bfloat16(b);
    __nv_bfloat16 la = __float2bfloat16(a - __bfloat162float(ha));
    __nv_bfloat16 lb = __float2bfloat16(b - __bfloat162float(hb));
    hi = (uint32_t)*(uint16_t*)&ha | ((uint32_t)*(uint16_t*)&hb << 16);
    lo = (uint32_t)*(uint16_t*)&la | ((uint32_t)*(uint16_t*)&lb << 16);
}
static __device__ __forceinline__ float silu_f(float x) {
    float e = __expf(-x);
    return x * __fdividef(1.0f, 1.0f + e);
}

__global__ void prep_kernel(const float* __restrict__ W1) {
    int t0 = blockIdx.x * blockDim.x + threadIdx.x;
    int stride = gridDim.x * blockDim.x;
    for (int idx = t0; idx < 64 * 256; idx += stride) {
        int k = idx >> 8, n = idx & 255;          // W1 is (64,256): W1[k][n]
        float v = W1[idx];
        __nv_bfloat16 h = __float2bfloat16(v);
        __nv_bfloat16 l = __float2bfloat16(v - __bfloat162float(h));
        uint32_t off = (uint32_t)(n * 128 + (((k >> 3) ^ (n & 7)) << 4) + (k & 7) * 2);
        *(uint16_t*)(g_B1 + off) = *(uint16_t*)&h;
        *(uint16_t*)(g_B1 + 32768 + off) = *(uint16_t*)&l;
    }
}

__global__ void __launch_bounds__(THREADS, 2)
relfeat_mma(const float* __restrict__ Q, const float* __restrict__ K,
            const float* __restrict__ b1, const float* __restrict__ W2,
            const float* __restrict__ b2, float* __restrict__ out) {
    extern __shared__ char sm[];
    const uint32_t smb = smem_u32(sm);
    const int t = threadIdx.x;
    const int w = t >> 5, lane = t & 31;
    const int g = lane >> 2, tq = lane & 3;
    const int bx = blockIdx.x;                 // 0..4095
    const int jb = bx & 1, i = (bx >> 1) & 255, b = bx >> 9;

    // ---- stage weights ----
    {
        const uint4* s1 = (const uint4*)g_B1;
        uint4* d1 = (uint4*)(sm + B1H_OFF);
        for (int idx = t; idx < 4096; idx += THREADS) d1[idx] = s1[idx];
        float4* w2d = (float4*)(sm + W2F_OFF);
        const float4* w2s = (const float4*)W2;
        for (int idx = t; idx < 512; idx += THREADS) w2d[idx] = w2s[idx];
        ((float*)(sm + B1V_OFF))[t] = b1[t];
        if (t < 8) ((float*)(sm + B2V_OFF))[t] = b2[t];
    }

    // ---- features: 2 threads per row (p = t&127, half = t>>7) ----
    {
        const int p = t & 127, half = t >> 7;
        const float* qr = Q + ((size_t)b * 256 + i) * 10;
        const float* kr = K + ((size_t)b * 256 + jb * 128 + p) * 10;
        float qpx = qr[3], qpy = qr[4], qvx = qr[5], qvy = qr[6];
        float dpx = kr[3] - qpx, dpy = kr[4] - qpy;
        float dvx = kr[5] - qvx, dvy = kr[6] - qvy;
        float dist = sqrtf(dpx * dpx + dpy * dpy + 1e-6f);
        float f[32];
        if (half == 0) {
            float inv_dist = 1.0f / (dist + 0.1f);
            float binv = 1.0f / (dist + 1e-6f);
            float bxn = dpx * binv, byn = dpy * binv;
            float ata = bxn * qr[7] + byn * qr[8];
            float aspect = bxn * kr[7] + byn * kr[8];
            const float in4[4] = { dist, inv_dist, ata, aspect };
            #pragma unroll
            for (int d = 0; d < 4; ++d)
                #pragma unroll
                for (int kk = 0; kk < 4; ++kk) {
                    float s, c;
                    __sincosf(in4[d] * (float)(1 << kk), &s, &c);
                    f[d * 8 + kk] = s; f[d * 8 + 4 + kk] = c;
                }
        } else {
            float dot = dpx * dvx + dpy * dvy;
            float ss = dvx * dvx + dvy * dvy;
            float ttca = tanhf(fmaxf(-dot / (ss + 1e-6f), 0.0f));
            float same = (qr[0] == kr[0]) ? 1.0f : 0.0f;
            float dspd = sqrtf(kr[5] * kr[5] + kr[6] * kr[6]) -
                         sqrtf(qvx * qvx + qvy * qvy);
            const float in2[8] = { dpx, dpy, dvx, dvy, ttca, dist, same, dspd };
            #pragma unroll
            for (int d = 0; d < 8; ++d)
                #pragma unroll
                for (int kk = 0; kk < 2; ++kk) {
                    float s, c;
                    __sincosf(in2[d] * (float)(1 << kk), &s, &c);
                    f[d * 4 + kk] = s; f[d * 4 + 2 + kk] = c;
                }
        }
        uint32_t hw[16], lw[16];
        #pragma unroll
        for (int e = 0; e < 16; ++e) split2(f[2 * e], f[2 * e + 1], hw[e], lw[e]);
        #pragma unroll
        for (int q = 0; q < 4; ++q) {
            uint32_t off = (uint32_t)(p * 144 + half * 64 + q * 16);
            *(uint4*)(sm + A_HI_OFF + off) =
                make_uint4(hw[4 * q], hw[4 * q + 1], hw[4 * q + 2], hw[4 * q + 3]);
            *(uint4*)(sm + A_LO_OFF + off) =
                make_uint4(lw[4 * q], lw[4 * q + 1], lw[4 * q + 2], lw[4 * q + 3]);
        }
    }
    __syncthreads();

    // ---- A fragments via ldmatrix: warp w covers rows w*16..w*16+15 ----
    uint32_t ah[4][4], al[4][4];
    #pragma unroll
    for (int s = 0; s < 4; ++s) {
        uint32_t row = (uint32_t)(w * 16 + (lane & 15));
        uint32_t addr = smb + A_HI_OFF + row * 144 + 32 * s + ((lane >> 4) & 1) * 16;
        LDMX4(ah[s], addr);
        LDMX4(al[s], addr + 18432);
    }

    const float* b1v = (const float*)(sm + B1V_OFF);
    const float* b2v = (const float*)(sm + B2V_OFF);
    float* hb = (float*)(sm + HBUF_OFF);
    const int r2 = t & 127, kh = t >> 7;       // GEMM2: row, k-half

    unsigned long long o0 = pack2(b2v[0], b2v[1]);
    unsigned long long o1 = pack2(b2v[2], b2v[3]);
    unsigned long long o2 = pack2(b2v[4], b2v[5]);
    unsigned long long o3 = pack2(b2v[6], b2v[7]);
    if (kh) { o0 = 0; o1 = 0; o2 = 0; o3 = 0; }   // bias counted once

    #pragma unroll 1
    for (int cch = 0; cch < 4; ++cch) {
        // ---- GEMM1 (bf16 hi/lo 3-chain): chunk [128 j][64 n] ----
        float acc[8][4];
        #pragma unroll
        for (int nt = 0; nt < 8; ++nt) {
            const int n0 = cch * 64 + nt * 8 + 2 * tq;
            acc[nt][0] = b1v[n0];  acc[nt][1] = b1v[n0 + 1];
            acc[nt][2] = b1v[n0];  acc[nt][3] = b1v[n0 + 1];
        }
        #pragma unroll
        for (int s = 0; s < 4; ++s)
            #pragma unroll
            for (int nt = 0; nt < 8; ++nt) {
                uint32_t brow = (uint32_t)(cch * 64 + nt * 8 + (lane & 7));
                uint32_t c16 = (uint32_t)(2 * s + ((lane >> 3) & 1));
                uint32_t baddr = smb + B1H_OFF + brow * 128 +
                                 ((c16 ^ (brow & 7)) << 4);
                uint32_t bh0, bh1, bl0, bl1;
                LDMX2(bh0, bh1, baddr);
                LDMX2(bl0, bl1, baddr + 32768);
                mma16816(acc[nt], ah[s], bh0, bh1);
                mma16816(acc[nt], ah[s], bl0, bl1);
                mma16816(acc[nt], al[s], bh0, bh1);
            }
        __syncthreads();   // prev GEMM2 HBUF reads / initial A-frag loads done
        // ---- silu -> HBUF ----
        {
            const int r = w * 16 + g;
            #pragma unroll
            for (int nt = 0; nt < 8; ++nt) {
                const int c2 = nt * 8 + 2 * tq;
                *(float2*)(hb + r * 68 + c2) =
                    make_float2(silu_f(acc[nt][0]), silu_f(acc[nt][1]));
                *(float2*)(hb + (r + 8) * 68 + c2) =
                    make_float2(silu_f(acc[nt][2]), silu_f(acc[nt][3]));
            }
        }
        __syncthreads();
        // ---- GEMM2 (scalar f32x2, k split over 2 threads/row) ----
        const float4* hrow = (const float4*)(hb + r2 * 68 + kh * 32);
        const float* w2f = (const float*)(sm + W2F_OFF) + (cch * 64 + kh * 32) * 8;
        #pragma unroll
        for (int kk = 0; kk < 8; ++kk) {
            const float4 hv = hrow[kk];
            const float he[4] = { hv.x, hv.y, hv.z, hv.w };
            #pragma unroll
            for (int e = 0; e < 4; ++e) {
                const int k = 4 * kk + e;
                const unsigned long long hh = pack2(he[e], he[e]);
                const ulonglong2 wa = *(const ulonglong2*)(w2f + k * 8);
                const ulonglong2 wb = *(const ulonglong2*)(w2f + k * 8 + 4);
                o0 = ffma2(hh, wa.x, o0);
                o1 = ffma2(hh, wa.y, o1);
                o2 = ffma2(hh, wb.x, o2);
                o3 = ffma2(hh, wb.y, o3);
            }
        }
    }

    // ---- cross-thread k-half reduction via PBUF (aliases dead B1L) ----
    float* pb = (float*)(sm + PBUF_OFF);
    if (kh) {
        float r8[8];
        unpack2(o0, r8[0], r8[1]); unpack2(o1, r8[2], r8[3]);
        unpack2(o2, r8[4], r8[5]); unpack2(o3, r8[6], r8[7]);
        *(float4*)(pb + r2 * 8)     = make_float4(r8[0], r8[1], r8[2], r8[3]);
        *(float4*)(pb + r2 * 8 + 4) = make_float4(r8[4], r8[5], r8[6], r8[7]);
    }
    __syncthreads();
    if (!kh) {
        float r8[8];
        unpack2(o0, r8[0], r8[1]); unpack2(o1, r8[2], r8[3]);
        unpack2(o2, r8[4], r8[5]); unpack2(o3, r8[6], r8[7]);
        const float4 pa = *(const float4*)(pb + r2 * 8);
        const float4 pbv = *(const float4*)(pb + r2 * 8 + 4);
        r8[0] += pa.x;  r8[1] += pa.y;  r8[2] += pa.z;  r8[3] += pa.w;
        r8[4] += pbv.x; r8[5] += pbv.y; r8[6] += pbv.z; r8[7] += pbv.w;
        const size_t base = (((size_t)b * 8) * 256 + i) * 256 + (size_t)(jb * 128 + r2);
        #pragma unroll
        for (int h = 0; h < 8; ++h)
            out[base + (size_t)h * 65536] = r8[h];
    }
}

extern "C" void kernel_launch(void* const* d_in, const int* in_sizes, int n_in,
                              void* d_out, int out_size) {
    const float* Q  = (const float*)d_in[0];
    const float* K  = (const float*)d_in[1];
    const float* W1 = (const float*)d_in[2];
    const float* b1 = (const float*)d_in[3];
    const float* W2 = (const float*)d_in[4];
    const float* b2 = (const float*)d_in[5];
    float* out = (float*)d_out;

    prep_kernel<<<16, THREADS>>>(W1);
    cudaFuncSetAttribute(relfeat_mma, cudaFuncAttributeMaxDynamicSharedMemorySize,
                         SMEM_BYTES);
    relfeat_mma<<<4096, THREADS, SMEM_BYTES>>>(Q, K, b1, W2, b2, out);
}

// round 7
// speedup vs baseline: 2.5991x; 1.2077x over previous
#include <cuda_runtime.h>
#include <cuda_bf16.h>
#include <cstdint>

#define THREADS 256

// prep-built W1^T bf16 image, XOR-swizzled rows of 128B: hi @0, lo @32768
__device__ __align__(16) uint8_t g_B1[65536];
// prep-built W2 mma B-frag pair image: u32[128 k2][8 n], hi @0, lo @4096
__device__ __align__(16) uint8_t g_W2[8192];

// smem byte offsets
#define A_HI_OFF   0        // feat hi [128][72 bf16], stride 144 (prologue only)
#define A_LO_OFF   18432
#define B1H_OFF    0        // aliases A after frag loads (swizzled 128B rows)
#define B1L_OFF    32768
#define W2F_OFF    65536    // u32 [128][8] hi, +4096 lo
#define B1V_OFF    73728    // 256 f32
#define B2V_OFF    74752    // 8 f32
#define SMEM_BYTES 74784

#define LDMX4(r, a) asm volatile( \
    "ldmatrix.sync.aligned.m8n8.x4.shared.b16 {%0,%1,%2,%3}, [%4];" \
    : "=r"((r)[0]), "=r"((r)[1]), "=r"((r)[2]), "=r"((r)[3]) : "r"(a))

static __device__ __forceinline__ uint32_t smem_u32(const void* p) {
    uint32_t a;
    asm("{ .reg .u64 t; cvta.to.shared.u64 t, %1; cvt.u32.u64 %0, t; }" : "=r"(a) : "l"(p));
    return a;
}
static __device__ __forceinline__ void mma16816(float* c, const uint32_t* a,
                                                uint32_t b0, uint32_t b1) {
    asm("mma.sync.aligned.m16n8k16.row.col.f32.bf16.bf16.f32 "
        "{%0,%1,%2,%3}, {%4,%5,%6,%7}, {%8,%9}, {%0,%1,%2,%3};"
        : "+f"(c[0]), "+f"(c[1]), "+f"(c[2]), "+f"(c[3])
        : "r"(a[0]), "r"(a[1]), "r"(a[2]), "r"(a[3]), "r"(b0), "r"(b1));
}
static __device__ __forceinline__ void split2(float a, float b, uint32_t& hi, uint32_t& lo) {
    __nv_bfloat16 ha = __float2bfloat16(a), hb = __float2bfloat16(b);
    __nv_bfloat16 la = __float2bfloat16(a - __bfloat162float(ha));
    __nv_bfloat16 lb = __float2bfloat16(b - __bfloat162float(hb));
    hi = (uint32_t)*(uint16_t*)&ha | ((uint32_t)*(uint16_t*)&hb << 16);
    lo = (uint32_t)*(uint16_t*)&la | ((uint32_t)*(uint16_t*)&lb << 16);
}
static __device__ __forceinline__ float silu_f(float x) {
    float e = __expf(-x);
    return x * __fdividef(1.0f, 1.0f + e);
}

__global__ void prep_kernel(const float* __restrict__ W1, const float* __restrict__ W2) {
    int t0 = blockIdx.x * blockDim.x + threadIdx.x;
    int stride = gridDim.x * blockDim.x;
    for (int idx = t0; idx < 64 * 256; idx += stride) {
        int k = idx >> 8, n = idx & 255;          // W1 is (64,256): W1[k][n]
        float v = W1[idx];
        __nv_bfloat16 h = __float2bfloat16(v);
        __nv_bfloat16 l = __float2bfloat16(v - __bfloat162float(h));
        uint32_t off = (uint32_t)(n * 128 + (((k >> 3) ^ (n & 7)) << 4) + (k & 7) * 2);
        *(uint16_t*)(g_B1 + off) = *(uint16_t*)&h;
        *(uint16_t*)(g_B1 + 32768 + off) = *(uint16_t*)&l;
    }
    for (int idx = t0; idx < 1024; idx += stride) {
        int k2 = idx >> 3, n = idx & 7;           // W2 is (256,8)
        uint32_t hi, lo;
        split2(W2[(2 * k2) * 8 + n], W2[(2 * k2 + 1) * 8 + n], hi, lo);
        ((uint32_t*)g_W2)[idx] = hi;
        ((uint32_t*)(g_W2 + 4096))[idx] = lo;
    }
}

__global__ void __launch_bounds__(THREADS, 2)
relfeat_mma(const float* __restrict__ Q, const float* __restrict__ K,
            const float* __restrict__ b1, const float* __restrict__ b2,
            float* __restrict__ out) {
    extern __shared__ char sm[];
    const uint32_t smb = smem_u32(sm);
    const int t = threadIdx.x;
    const int w = t >> 5, lane = t & 31;
    const int g = lane >> 2, tq = lane & 3;
    const int bx = blockIdx.x;                 // 0..4095
    const int jb = bx & 1, i = (bx >> 1) & 255, b = bx >> 9;

    // ---- stage W2 frags / biases (region disjoint from A planes) ----
    {
        const uint4* s2 = (const uint4*)g_W2;
        uint4* d2 = (uint4*)(sm + W2F_OFF);
        for (int idx = t; idx < 512; idx += THREADS) d2[idx] = s2[idx];
        ((float*)(sm + B1V_OFF))[t] = b1[t];
        if (t < 8) ((float*)(sm + B2V_OFF))[t] = b2[t];
    }

    // ---- features: 2 threads per row (p = t&127, half = t>>7) ----
    {
        const int p = t & 127, half = t >> 7;
        const float* qr = Q + ((size_t)b * 256 + i) * 10;
        const float* kr = K + ((size_t)b * 256 + jb * 128 + p) * 10;
        float qpx = qr[3], qpy = qr[4], qvx = qr[5], qvy = qr[6];
        float dpx = kr[3] - qpx, dpy = kr[4] - qpy;
        float dvx = kr[5] - qvx, dvy = kr[6] - qvy;
        float dist = sqrtf(dpx * dpx + dpy * dpy + 1e-6f);
        float f[32];
        if (half == 0) {
            float inv_dist = 1.0f / (dist + 0.1f);
            float binv = 1.0f / (dist + 1e-6f);
            float bxn = dpx * binv, byn = dpy * binv;
            float ata = bxn * qr[7] + byn * qr[8];
            float aspect = bxn * kr[7] + byn * kr[8];
            const float in4[4] = { dist, inv_dist, ata, aspect };
            #pragma unroll
            for (int d = 0; d < 4; ++d)
                #pragma unroll
                for (int kk = 0; kk < 4; ++kk) {
                    float s, c;
                    __sincosf(in4[d] * (float)(1 << kk), &s, &c);
                    f[d * 8 + kk] = s; f[d * 8 + 4 + kk] = c;
                }
        } else {
            float dot = dpx * dvx + dpy * dvy;
            float ss = dvx * dvx + dvy * dvy;
            float ttca = tanhf(fmaxf(-dot / (ss + 1e-6f), 0.0f));
            float same = (qr[0] == kr[0]) ? 1.0f : 0.0f;
            float dspd = sqrtf(kr[5] * kr[5] + kr[6] * kr[6]) -
                         sqrtf(qvx * qvx + qvy * qvy);
            const float in2[8] = { dpx, dpy, dvx, dvy, ttca, dist, same, dspd };
            #pragma unroll
            for (int d = 0; d < 8; ++d)
                #pragma unroll
                for (int kk = 0; kk < 2; ++kk) {
                    float s, c;
                    __sincosf(in2[d] * (float)(1 << kk), &s, &c);
                    f[d * 4 + kk] = s; f[d * 4 + 2 + kk] = c;
                }
        }
        uint32_t hw[16], lw[16];
        #pragma unroll
        for (int e = 0; e < 16; ++e) split2(f[2 * e], f[2 * e + 1], hw[e], lw[e]);
        #pragma unroll
        for (int q = 0; q < 4; ++q) {
            uint32_t off = (uint32_t)(p * 144 + half * 64 + q * 16);
            *(uint4*)(sm + A_HI_OFF + off) =
                make_uint4(hw[4 * q], hw[4 * q + 1], hw[4 * q + 2], hw[4 * q + 3]);
            *(uint4*)(sm + A_LO_OFF + off) =
                make_uint4(lw[4 * q], lw[4 * q + 1], lw[4 * q + 2], lw[4 * q + 3]);
        }
    }
    __syncthreads();

    // ---- A fragments via ldmatrix: warp w owns rows w*16..w*16+15 ----
    uint32_t ah[4][4], al[4][4];
    #pragma unroll
    for (int s = 0; s < 4; ++s) {
        uint32_t row = (uint32_t)(w * 16 + (lane & 15));
        uint32_t addr = smb + A_HI_OFF + row * 144 + 32 * s + ((lane >> 4) & 1) * 16;
        LDMX4(ah[s], addr);
        LDMX4(al[s], addr + 18432);
    }
    __syncthreads();   // A region consumed by all warps

    // ---- stage B1 into region aliasing A ----
    {
        const uint4* s1 = (const uint4*)g_B1;
        uint4* d1 = (uint4*)(sm + B1H_OFF);
        for (int idx = t; idx < 4096; idx += THREADS) d1[idx] = s1[idx];
    }
    __syncthreads();

    const float* b1v = (const float*)(sm + B1V_OFF);
    const float* b2v = (const float*)(sm + B2V_OFF);
    const uint32_t* w2h = (const uint32_t*)(sm + W2F_OFF);
    const uint32_t* w2l = (const uint32_t*)(sm + W2F_OFF + 4096);

    // output accumulators: D[g][2tq..], D[g+8][2tq..] with bias once
    float o[4];
    o[0] = b2v[2 * tq]; o[1] = b2v[2 * tq + 1]; o[2] = o[0]; o[3] = o[1];

    #pragma unroll 1
    for (int cch = 0; cch < 4; ++cch) {
        // ---- GEMM1 (bf16 hi/lo 3-chain), chunk n = cch*64..+63 ----
        float acc[8][4];
        #pragma unroll
        for (int nt = 0; nt < 8; ++nt) {
            const float2 bb = *(const float2*)(b1v + cch * 64 + nt * 8 + 2 * tq);
            acc[nt][0] = bb.x; acc[nt][1] = bb.y;
            acc[nt][2] = bb.x; acc[nt][3] = bb.y;
        }
        #pragma unroll
        for (int s2m = 0; s2m < 2; ++s2m)
            #pragma unroll
            for (int nt = 0; nt < 8; ++nt) {
                uint32_t brow = (uint32_t)(cch * 64 + nt * 8 + (lane & 7));
                uint32_t c16 = (uint32_t)(4 * s2m + (lane >> 3));
                uint32_t baddr = smb + B1H_OFF + brow * 128 +
                                 ((c16 ^ (brow & 7)) << 4);
                uint32_t bh[4], bl[4];
                LDMX4(bh, baddr);
                LDMX4(bl, baddr + 32768);
                const int s = 2 * s2m;
                mma16816(acc[nt], ah[s], bh[0], bh[1]);
                mma16816(acc[nt], ah[s], bl[0], bl[1]);
                mma16816(acc[nt], al[s], bh[0], bh[1]);
                mma16816(acc[nt], ah[s + 1], bh[2], bh[3]);
                mma16816(acc[nt], ah[s + 1], bl[2], bl[3]);
                mma16816(acc[nt], al[s + 1], bh[2], bh[3]);
            }
        // ---- silu + GEMM2 directly in registers (k = cch*64..+63) ----
        #pragma unroll
        for (int s2 = 0; s2 < 4; ++s2) {
            const int kw = (cch * 32 + 8 * s2 + tq) * 8 + g;
            const uint32_t b0h = w2h[kw], b1h = w2h[kw + 32];
            const uint32_t b0l = w2l[kw], b1l = w2l[kw + 32];
            float h0 = silu_f(acc[2 * s2][0]);
            float h1 = silu_f(acc[2 * s2][1]);
            float h2 = silu_f(acc[2 * s2][2]);
            float h3 = silu_f(acc[2 * s2][3]);
            float h4 = silu_f(acc[2 * s2 + 1][0]);
            float h5 = silu_f(acc[2 * s2 + 1][1]);
            float h6 = silu_f(acc[2 * s2 + 1][2]);
            float h7 = silu_f(acc[2 * s2 + 1][3]);
            uint32_t a2h[4], a2l[4];
            split2(h0, h1, a2h[0], a2l[0]);
            split2(h2, h3, a2h[1], a2l[1]);
            split2(h4, h5, a2h[2], a2l[2]);
            split2(h6, h7, a2h[3], a2l[3]);
            mma16816(o, a2h, b0h, b1h);
            mma16816(o, a2h, b0l, b1l);
            mma16816(o, a2l, b0h, b1h);
        }
    }

    // ---- store out[b,h,i,j]: rows w*16+g, w*16+8+g; heads 2tq, 2tq+1 ----
    {
        const int j0 = jb * 128 + w * 16 + g;
        const size_t p0 = (((size_t)(b * 8 + 2 * tq)) * 256 + i) * 256 + j0;
        const size_t p1 = (((size_t)(b * 8 + 2 * tq + 1)) * 256 + i) * 256 + j0;
        out[p0]     = o[0];
        out[p1]     = o[1];
        out[p0 + 8] = o[2];
        out[p1 + 8] = o[3];
    }
}

extern "C" void kernel_launch(void* const* d_in, const int* in_sizes, int n_in,
                              void* d_out, int out_size) {
    const float* Q  = (const float*)d_in[0];
    const float* K  = (const float*)d_in[1];
    const float* W1 = (const float*)d_in[2];
    const float* b1 = (const float*)d_in[3];
    const float* W2 = (const float*)d_in[4];
    const float* b2 = (const float*)d_in[5];
    float* out = (float*)d_out;

    prep_kernel<<<16, THREADS>>>(W1, W2);
    cudaFuncSetAttribute(relfeat_mma, cudaFuncAttributeMaxDynamicSharedMemorySize,
                         SMEM_BYTES);
    relfeat_mma<<<4096, THREADS, SMEM_BYTES>>>(Q, K, b1, b2, out);
}

// round 8
// speedup vs baseline: 3.6524x; 1.4053x over previous
#include <cuda_runtime.h>
#include <cuda_fp16.h>
#include <cstdint>

#define THREADS 256

// prep-built W1^T fp16 image, XOR-swizzled rows of 128B: hi @0, lo @32768
__device__ __align__(16) uint8_t g_B1[65536];
// prep-built W2 mma B-frag pair image: u32[128 k2][8 n], hi @0, lo @4096
__device__ __align__(16) uint8_t g_W2[8192];

// smem byte offsets
#define A_OFF      0        // feat fp16 [128][72], stride 144 (prologue only)
#define B1H_OFF    0        // aliases A after frag loads (swizzled 128B rows)
#define B1L_OFF    32768
#define W2F_OFF    65536    // u32 [128][8] hi, +4096 lo
#define B1V_OFF    73728    // 256 f32
#define B2V_OFF    74752    // 8 f32
#define SMEM_BYTES 74784

#define LDMX4(r, a) asm volatile( \
    "ldmatrix.sync.aligned.m8n8.x4.shared.b16 {%0,%1,%2,%3}, [%4];" \
    : "=r"((r)[0]), "=r"((r)[1]), "=r"((r)[2]), "=r"((r)[3]) : "r"(a))

static __device__ __forceinline__ uint32_t smem_u32(const void* p) {
    uint32_t a;
    asm("{ .reg .u64 t; cvta.to.shared.u64 t, %1; cvt.u32.u64 %0, t; }" : "=r"(a) : "l"(p));
    return a;
}
static __device__ __forceinline__ void mma16816(float* c, const uint32_t* a,
                                                uint32_t b0, uint32_t b1) {
    asm("mma.sync.aligned.m16n8k16.row.col.f32.f16.f16.f32 "
        "{%0,%1,%2,%3}, {%4,%5,%6,%7}, {%8,%9}, {%0,%1,%2,%3};"
        : "+f"(c[0]), "+f"(c[1]), "+f"(c[2]), "+f"(c[3])
        : "r"(a[0]), "r"(a[1]), "r"(a[2]), "r"(a[3]), "r"(b0), "r"(b1));
}
// pack two f32 into f16x2: low half = x, high half = y
static __device__ __forceinline__ uint32_t packh2(float x, float y) {
    uint32_t r;
    asm("cvt.rn.f16x2.f32 %0, %1, %2;" : "=r"(r) : "f"(y), "f"(x));
    return r;
}
static __device__ __forceinline__ float silu_f(float x) {
    float e = __expf(-x);
    return x * __fdividef(1.0f, 1.0f + e);
}

__global__ void prep_kernel(const float* __restrict__ W1, const float* __restrict__ W2) {
    int t0 = blockIdx.x * blockDim.x + threadIdx.x;
    int stride = gridDim.x * blockDim.x;
    for (int idx = t0; idx < 64 * 256; idx += stride) {
        int k = idx >> 8, n = idx & 255;          // W1 is (64,256): W1[k][n]
        float v = W1[idx];
        __half h = __float2half_rn(v);
        __half l = __float2half_rn(v - __half2float(h));
        uint32_t off = (uint32_t)(n * 128 + (((k >> 3) ^ (n & 7)) << 4) + (k & 7) * 2);
        *(uint16_t*)(g_B1 + off) = *(uint16_t*)&h;
        *(uint16_t*)(g_B1 + 32768 + off) = *(uint16_t*)&l;
    }
    for (int idx = t0; idx < 1024; idx += stride) {
        int k2 = idx >> 3, n = idx & 7;           // W2 is (256,8)
        float v0 = W2[(2 * k2) * 8 + n], v1 = W2[(2 * k2 + 1) * 8 + n];
        __half h0 = __float2half_rn(v0), h1 = __float2half_rn(v1);
        __half l0 = __float2half_rn(v0 - __half2float(h0));
        __half l1 = __float2half_rn(v1 - __half2float(h1));
        ((uint32_t*)g_W2)[idx] =
            (uint32_t)*(uint16_t*)&h0 | ((uint32_t)*(uint16_t*)&h1 << 16);
        ((uint32_t*)(g_W2 + 4096))[idx] =
            (uint32_t)*(uint16_t*)&l0 | ((uint32_t)*(uint16_t*)&l1 << 16);
    }
}

__global__ void __launch_bounds__(THREADS, 2)
relfeat_mma(const float* __restrict__ Q, const float* __restrict__ K,
            const float* __restrict__ b1, const float* __restrict__ b2,
            float* __restrict__ out) {
    extern __shared__ char sm[];
    const uint32_t smb = smem_u32(sm);
    const int t = threadIdx.x;
    const int w = t >> 5, lane = t & 31;
    const int g = lane >> 2, tq = lane & 3;
    const int bx = blockIdx.x;                 // 0..4095
    const int jb = bx & 1, i = (bx >> 1) & 255, b = bx >> 9;

    // ---- stage W2 frags / biases (disjoint from A region) ----
    {
        const uint4* s2 = (const uint4*)g_W2;
        uint4* d2 = (uint4*)(sm + W2F_OFF);
        for (int idx = t; idx < 512; idx += THREADS) d2[idx] = s2[idx];
        ((float*)(sm + B1V_OFF))[t] = b1[t];
        if (t < 8) ((float*)(sm + B2V_OFF))[t] = b2[t];
    }

    // ---- features: 2 threads per row (p = t&127, half = t>>7) ----
    {
        const int p = t & 127, half = t >> 7;
        const float* qr = Q + ((size_t)b * 256 + i) * 10;
        const float* kr = K + ((size_t)b * 256 + jb * 128 + p) * 10;
        float qpx = qr[3], qpy = qr[4], qvx = qr[5], qvy = qr[6];
        float dpx = kr[3] - qpx, dpy = kr[4] - qpy;
        float dvx = kr[5] - qvx, dvy = kr[6] - qvy;
        float dist = sqrtf(dpx * dpx + dpy * dpy + 1e-6f);
        float f[32];
        if (half == 0) {
            float inv_dist = 1.0f / (dist + 0.1f);
            float binv = 1.0f / (dist + 1e-6f);
            float bxn = dpx * binv, byn = dpy * binv;
            float ata = bxn * qr[7] + byn * qr[8];
            float aspect = bxn * kr[7] + byn * kr[8];
            const float in4[4] = { dist, inv_dist, ata, aspect };
            #pragma unroll
            for (int d = 0; d < 4; ++d)
                #pragma unroll
                for (int kk = 0; kk < 4; ++kk) {
                    float s, c;
                    __sincosf(in4[d] * (float)(1 << kk), &s, &c);
                    f[d * 8 + kk] = s; f[d * 8 + 4 + kk] = c;
                }
        } else {
            float dot = dpx * dvx + dpy * dvy;
            float ss = dvx * dvx + dvy * dvy;
            float ttca = tanhf(fmaxf(-dot / (ss + 1e-6f), 0.0f));
            float same = (qr[0] == kr[0]) ? 1.0f : 0.0f;
            float dspd = sqrtf(kr[5] * kr[5] + kr[6] * kr[6]) -
                         sqrtf(qvx * qvx + qvy * qvy);
            const float in2[8] = { dpx, dpy, dvx, dvy, ttca, dist, same, dspd };
            #pragma unroll
            for (int d = 0; d < 8; ++d)
                #pragma unroll
                for (int kk = 0; kk < 2; ++kk) {
                    float s, c;
                    __sincosf(in2[d] * (float)(1 << kk), &s, &c);
                    f[d * 4 + kk] = s; f[d * 4 + 2 + kk] = c;
                }
        }
        uint32_t hw[16];
        #pragma unroll
        for (int e = 0; e < 16; ++e) hw[e] = packh2(f[2 * e], f[2 * e + 1]);
        #pragma unroll
        for (int q = 0; q < 4; ++q) {
            uint32_t off = (uint32_t)(p * 144 + half * 64 + q * 16);
            *(uint4*)(sm + A_OFF + off) =
                make_uint4(hw[4 * q], hw[4 * q + 1], hw[4 * q + 2], hw[4 * q + 3]);
        }
    }
    __syncthreads();

    // ---- A fragments via ldmatrix: warp w owns rows w*16..w*16+15 ----
    uint32_t ah[4][4];
    #pragma unroll
    for (int s = 0; s < 4; ++s) {
        uint32_t row = (uint32_t)(w * 16 + (lane & 15));
        uint32_t addr = smb + A_OFF + row * 144 + 32 * s + ((lane >> 4) & 1) * 16;
        LDMX4(ah[s], addr);
    }
    __syncthreads();   // A region consumed by all warps

    // ---- stage B1 into region aliasing A ----
    {
        const uint4* s1 = (const uint4*)g_B1;
        uint4* d1 = (uint4*)(sm + B1H_OFF);
        for (int idx = t; idx < 4096; idx += THREADS) d1[idx] = s1[idx];
    }
    __syncthreads();

    const float* b1v = (const float*)(sm + B1V_OFF);
    const float* b2v = (const float*)(sm + B2V_OFF);
    const uint32_t* w2h = (const uint32_t*)(sm + W2F_OFF);
    const uint32_t* w2l = (const uint32_t*)(sm + W2F_OFF + 4096);

    // output accumulators: D[g][2tq..], D[g+8][2tq..] with bias once
    float o[4];
    o[0] = b2v[2 * tq]; o[1] = b2v[2 * tq + 1]; o[2] = o[0]; o[3] = o[1];

    #pragma unroll 1
    for (int cch = 0; cch < 4; ++cch) {
        // ---- GEMM1 (fp16 A, W hi/lo 2-chain), chunk n = cch*64..+63 ----
        float acc[8][4];
        #pragma unroll
        for (int nt = 0; nt < 8; ++nt) {
            const float2 bb = *(const float2*)(b1v + cch * 64 + nt * 8 + 2 * tq);
            acc[nt][0] = bb.x; acc[nt][1] = bb.y;
            acc[nt][2] = bb.x; acc[nt][3] = bb.y;
        }
        #pragma unroll
        for (int s2m = 0; s2m < 2; ++s2m)
            #pragma unroll
            for (int nt = 0; nt < 8; ++nt) {
                uint32_t brow = (uint32_t)(cch * 64 + nt * 8 + (lane & 7));
                uint32_t c16 = (uint32_t)(4 * s2m + (lane >> 3));
                uint32_t baddr = smb + B1H_OFF + brow * 128 +
                                 ((c16 ^ (brow & 7)) << 4);
                uint32_t bh[4], bl[4];
                LDMX4(bh, baddr);
                LDMX4(bl, baddr + 32768);
                const int s = 2 * s2m;
                mma16816(acc[nt], ah[s], bh[0], bh[1]);
                mma16816(acc[nt], ah[s], bl[0], bl[1]);
                mma16816(acc[nt], ah[s + 1], bh[2], bh[3]);
                mma16816(acc[nt], ah[s + 1], bl[2], bl[3]);
            }
        // ---- silu + GEMM2 in registers (k = cch*64..+63) ----
        #pragma unroll
        for (int s2 = 0; s2 < 4; ++s2) {
            const int kw = (cch * 32 + 8 * s2 + tq) * 8 + g;
            const uint32_t b0h = w2h[kw], b1h = w2h[kw + 32];
            const uint32_t b0l = w2l[kw], b1l = w2l[kw + 32];
            uint32_t a2[4];
            a2[0] = packh2(silu_f(acc[2 * s2][0]),     silu_f(acc[2 * s2][1]));
            a2[1] = packh2(silu_f(acc[2 * s2][2]),     silu_f(acc[2 * s2][3]));
            a2[2] = packh2(silu_f(acc[2 * s2 + 1][0]), silu_f(acc[2 * s2 + 1][1]));
            a2[3] = packh2(silu_f(acc[2 * s2 + 1][2]), silu_f(acc[2 * s2 + 1][3]));
            mma16816(o, a2, b0h, b1h);
            mma16816(o, a2, b0l, b1l);
        }
    }

    // ---- store out[b,h,i,j]: rows w*16+g, w*16+8+g; heads 2tq, 2tq+1 ----
    {
        const int j0 = jb * 128 + w * 16 + g;
        const size_t p0 = (((size_t)(b * 8 + 2 * tq)) * 256 + i) * 256 + j0;
        const size_t p1 = (((size_t)(b * 8 + 2 * tq + 1)) * 256 + i) * 256 + j0;
        out[p0]     = o[0];
        out[p1]     = o[1];
        out[p0 + 8] = o[2];
        out[p1 + 8] = o[3];
    }
}

extern "C" void kernel_launch(void* const* d_in, const int* in_sizes, int n_in,
                              void* d_out, int out_size) {
    const float* Q  = (const float*)d_in[0];
    const float* K  = (const float*)d_in[1];
    const float* W1 = (const float*)d_in[2];
    const float* b1 = (const float*)d_in[3];
    const float* W2 = (const float*)d_in[4];
    const float* b2 = (const float*)d_in[5];
    float* out = (float*)d_out;

    prep_kernel<<<16, THREADS>>>(W1, W2);
    cudaFuncSetAttribute(relfeat_mma, cudaFuncAttributeMaxDynamicSharedMemorySize,
                         SMEM_BYTES);
    relfeat_mma<<<4096, THREADS, SMEM_BYTES>>>(Q, K, b1, b2, out);
}

// round 9
// speedup vs baseline: 6.3087x; 1.7273x over previous
#include <cuda_runtime.h>
#include <cuda_fp16.h>
#include <cstdint>

#define THREADS 256

// prep-built W1^T fp16 image (hi only), XOR-swizzled rows of 128B
__device__ __align__(16) uint8_t g_B1[32768];
// prep-built W2 mma B-frag pair image: u32[128 k2][8 n], hi @0, lo @4096
__device__ __align__(16) uint8_t g_W2[8192];

// smem byte offsets
#define A_OFF      0        // feat fp16 [128][72], stride 144 (prologue only)
#define B1H_OFF    0        // aliases A after frag loads (swizzled 128B rows)
#define W2F_OFF    32768    // u32 [128][8] hi, +4096 lo
#define B1V_OFF    40960    // 256 f32
#define B2V_OFF    41984    // 8 f32
#define SMEM_BYTES 42016

#define LDMX4(r, a) asm volatile( \
    "ldmatrix.sync.aligned.m8n8.x4.shared.b16 {%0,%1,%2,%3}, [%4];" \
    : "=r"((r)[0]), "=r"((r)[1]), "=r"((r)[2]), "=r"((r)[3]) : "r"(a))

static __device__ __forceinline__ uint32_t smem_u32(const void* p) {
    uint32_t a;
    asm("{ .reg .u64 t; cvta.to.shared.u64 t, %1; cvt.u32.u64 %0, t; }" : "=r"(a) : "l"(p));
    return a;
}
static __device__ __forceinline__ void mma16816(float* c, const uint32_t* a,
                                                uint32_t b0, uint32_t b1) {
    asm("mma.sync.aligned.m16n8k16.row.col.f32.f16.f16.f32 "
        "{%0,%1,%2,%3}, {%4,%5,%6,%7}, {%8,%9}, {%0,%1,%2,%3};"
        : "+f"(c[0]), "+f"(c[1]), "+f"(c[2]), "+f"(c[3])
        : "r"(a[0]), "r"(a[1]), "r"(a[2]), "r"(a[3]), "r"(b0), "r"(b1));
}
// pack two f32 into f16x2: low half = x, high half = y
static __device__ __forceinline__ uint32_t packh2(float x, float y) {
    uint32_t r;
    asm("cvt.rn.f16x2.f32 %0, %1, %2;" : "=r"(r) : "f"(y), "f"(x));
    return r;
}
// silu via single-MUFU tanh: x*sigmoid(x) = 0.5x + 0.5x*tanh(x/2)
static __device__ __forceinline__ float silu_f(float x) {
    float hx = 0.5f * x, t;
    asm("tanh.approx.f32 %0, %1;" : "=f"(t) : "f"(hx));
    return fmaf(hx, t, hx);
}
// exact silu for the prologue's tanhf use stays library tanhf

__global__ void prep_kernel(const float* __restrict__ W1, const float* __restrict__ W2) {
    int t0 = blockIdx.x * blockDim.x + threadIdx.x;
    int stride = gridDim.x * blockDim.x;
    for (int idx = t0; idx < 64 * 256; idx += stride) {
        int k = idx >> 8, n = idx & 255;          // W1 is (64,256): W1[k][n]
        __half h = __float2half_rn(W1[idx]);
        uint32_t off = (uint32_t)(n * 128 + (((k >> 3) ^ (n & 7)) << 4) + (k & 7) * 2);
        *(uint16_t*)(g_B1 + off) = *(uint16_t*)&h;
    }
    for (int idx = t0; idx < 1024; idx += stride) {
        int k2 = idx >> 3, n = idx & 7;           // W2 is (256,8)
        float v0 = W2[(2 * k2) * 8 + n], v1 = W2[(2 * k2 + 1) * 8 + n];
        __half h0 = __float2half_rn(v0), h1 = __float2half_rn(v1);
        __half l0 = __float2half_rn(v0 - __half2float(h0));
        __half l1 = __float2half_rn(v1 - __half2float(h1));
        ((uint32_t*)g_W2)[idx] =
            (uint32_t)*(uint16_t*)&h0 | ((uint32_t)*(uint16_t*)&h1 << 16);
        ((uint32_t*)(g_W2 + 4096))[idx] =
            (uint32_t)*(uint16_t*)&l0 | ((uint32_t)*(uint16_t*)&l1 << 16);
    }
}

__global__ void __launch_bounds__(THREADS, 2)
relfeat_mma(const float* __restrict__ Q, const float* __restrict__ K,
            const float* __restrict__ b1, const float* __restrict__ b2,
            float* __restrict__ out) {
    extern __shared__ char sm[];
    const uint32_t smb = smem_u32(sm);
    const int t = threadIdx.x;
    const int w = t >> 5, lane = t & 31;
    const int g = lane >> 2, tq = lane & 3;
    const int bx = blockIdx.x;                 // 0..4095
    const int jb = bx & 1, i = (bx >> 1) & 255, b = bx >> 9;

    // ---- stage W2 frags / biases (disjoint from A region) ----
    {
        const uint4* s2 = (const uint4*)g_W2;
        uint4* d2 = (uint4*)(sm + W2F_OFF);
        for (int idx = t; idx < 512; idx += THREADS) d2[idx] = s2[idx];
        ((float*)(sm + B1V_OFF))[t] = b1[t];
        if (t < 8) ((float*)(sm + B2V_OFF))[t] = b2[t];
    }

    // ---- features: 2 threads per row (p = t&127, half = t>>7) ----
    {
        const int p = t & 127, half = t >> 7;
        const float* qr = Q + ((size_t)b * 256 + i) * 10;
        const float* kr = K + ((size_t)b * 256 + jb * 128 + p) * 10;
        float qpx = qr[3], qpy = qr[4], qvx = qr[5], qvy = qr[6];
        float dpx = kr[3] - qpx, dpy = kr[4] - qpy;
        float dvx = kr[5] - qvx, dvy = kr[6] - qvy;
        float dist = sqrtf(dpx * dpx + dpy * dpy + 1e-6f);
        float f[32];
        if (half == 0) {
            float inv_dist = 1.0f / (dist + 0.1f);
            float binv = 1.0f / (dist + 1e-6f);
            float bxn = dpx * binv, byn = dpy * binv;
            float ata = bxn * qr[7] + byn * qr[8];
            float aspect = bxn * kr[7] + byn * kr[8];
            const float in4[4] = { dist, inv_dist, ata, aspect };
            #pragma unroll
            for (int d = 0; d < 4; ++d)
                #pragma unroll
                for (int kk = 0; kk < 4; ++kk) {
                    float s, c;
                    __sincosf(in4[d] * (float)(1 << kk), &s, &c);
                    f[d * 8 + kk] = s; f[d * 8 + 4 + kk] = c;
                }
        } else {
            float dot = dpx * dvx + dpy * dvy;
            float ss = dvx * dvx + dvy * dvy;
            float ttca = tanhf(fmaxf(-dot / (ss + 1e-6f), 0.0f));
            float same = (qr[0] == kr[0]) ? 1.0f : 0.0f;
            float dspd = sqrtf(kr[5] * kr[5] + kr[6] * kr[6]) -
                         sqrtf(qvx * qvx + qvy * qvy);
            const float in2[8] = { dpx, dpy, dvx, dvy, ttca, dist, same, dspd };
            #pragma unroll
            for (int d = 0; d < 8; ++d)
                #pragma unroll
                for (int kk = 0; kk < 2; ++kk) {
                    float s, c;
                    __sincosf(in2[d] * (float)(1 << kk), &s, &c);
                    f[d * 4 + kk] = s; f[d * 4 + 2 + kk] = c;
                }
        }
        uint32_t hw[16];
        #pragma unroll
        for (int e = 0; e < 16; ++e) hw[e] = packh2(f[2 * e], f[2 * e + 1]);
        #pragma unroll
        for (int q = 0; q < 4; ++q) {
            uint32_t off = (uint32_t)(p * 144 + half * 64 + q * 16);
            *(uint4*)(sm + A_OFF + off) =
                make_uint4(hw[4 * q], hw[4 * q + 1], hw[4 * q + 2], hw[4 * q + 3]);
        }
    }
    __syncthreads();

    // ---- A fragments via ldmatrix: warp w owns rows w*16..w*16+15 ----
    uint32_t ah[4][4];
    #pragma unroll
    for (int s = 0; s < 4; ++s) {
        uint32_t row = (uint32_t)(w * 16 + (lane & 15));
        uint32_t addr = smb + A_OFF + row * 144 + 32 * s + ((lane >> 4) & 1) * 16;
        LDMX4(ah[s], addr);
    }
    __syncthreads();   // A region consumed by all warps

    // ---- stage B1 (hi only) into region aliasing A ----
    {
        const uint4* s1 = (const uint4*)g_B1;
        uint4* d1 = (uint4*)(sm + B1H_OFF);
        for (int idx = t; idx < 2048; idx += THREADS) d1[idx] = s1[idx];
    }
    __syncthreads();

    const float* b1v = (const float*)(sm + B1V_OFF);
    const float* b2v = (const float*)(sm + B2V_OFF);
    const uint32_t* w2h = (const uint32_t*)(sm + W2F_OFF);
    const uint32_t* w2l = (const uint32_t*)(sm + W2F_OFF + 4096);

    // output accumulators: D[g][2tq..], D[g+8][2tq..] with bias once
    float o[4];
    o[0] = b2v[2 * tq]; o[1] = b2v[2 * tq + 1]; o[2] = o[0]; o[3] = o[1];

    #pragma unroll 1
    for (int cch = 0; cch < 4; ++cch) {
        // ---- GEMM1 (fp16 A, fp16 W hi only), chunk n = cch*64..+63 ----
        float acc[8][4];
        #pragma unroll
        for (int nt = 0; nt < 8; ++nt) {
            const float2 bb = *(const float2*)(b1v + cch * 64 + nt * 8 + 2 * tq);
            acc[nt][0] = bb.x; acc[nt][1] = bb.y;
            acc[nt][2] = bb.x; acc[nt][3] = bb.y;
        }
        #pragma unroll
        for (int s2m = 0; s2m < 2; ++s2m)
            #pragma unroll
            for (int nt = 0; nt < 8; ++nt) {
                uint32_t brow = (uint32_t)(cch * 64 + nt * 8 + (lane & 7));
                uint32_t c16 = (uint32_t)(4 * s2m + (lane >> 3));
                uint32_t baddr = smb + B1H_OFF + brow * 128 +
                                 ((c16 ^ (brow & 7)) << 4);
                uint32_t bh[4];
                LDMX4(bh, baddr);
                const int s = 2 * s2m;
                mma16816(acc[nt], ah[s],     bh[0], bh[1]);
                mma16816(acc[nt], ah[s + 1], bh[2], bh[3]);
            }
        // ---- silu (1-MUFU tanh form) + GEMM2 in registers ----
        #pragma unroll
        for (int s2 = 0; s2 < 4; ++s2) {
            const int kw = (cch * 32 + 8 * s2 + tq) * 8 + g;
            const uint32_t b0h = w2h[kw], b1h = w2h[kw + 32];
            const uint32_t b0l = w2l[kw], b1l = w2l[kw + 32];
            uint32_t a2[4];
            a2[0] = packh2(silu_f(acc[2 * s2][0]),     silu_f(acc[2 * s2][1]));
            a2[1] = packh2(silu_f(acc[2 * s2][2]),     silu_f(acc[2 * s2][3]));
            a2[2] = packh2(silu_f(acc[2 * s2 + 1][0]), silu_f(acc[2 * s2 + 1][1]));
            a2[3] = packh2(silu_f(acc[2 * s2 + 1][2]), silu_f(acc[2 * s2 + 1][3]));
            mma16816(o, a2, b0h, b1h);
            mma16816(o, a2, b0l, b1l);
        }
    }

    // ---- store out[b,h,i,j]: rows w*16+g, w*16+8+g; heads 2tq, 2tq+1 ----
    {
        const int j0 = jb * 128 + w * 16 + g;
        const size_t p0 = (((size_t)(b * 8 + 2 * tq)) * 256 + i) * 256 + j0;
        const size_t p1 = (((size_t)(b * 8 + 2 * tq + 1)) * 256 + i) * 256 + j0;
        out[p0]     = o[0];
        out[p1]     = o[1];
        out[p0 + 8] = o[2];
        out[p1 + 8] = o[3];
    }
}

extern "C" void kernel_launch(void* const* d_in, const int* in_sizes, int n_in,
                              void* d_out, int out_size) {
    const float* Q  = (const float*)d_in[0];
    const float* K  = (const float*)d_in[1];
    const float* W1 = (const float*)d_in[2];
    const float* b1 = (const float*)d_in[3];
    const float* W2 = (const float*)d_in[4];
    const float* b2 = (const float*)d_in[5];
    float* out = (float*)d_out;

    prep_kernel<<<16, THREADS>>>(W1, W2);
    cudaFuncSetAttribute(relfeat_mma, cudaFuncAttributeMaxDynamicSharedMemorySize,
                         SMEM_BYTES);
    relfeat_mma<<<4096, THREADS, SMEM_BYTES>>>(Q, K, b1, b2, out);
}

// round 10
// speedup vs baseline: 7.7035x; 1.2211x over previous
#include <cuda_runtime.h>
#include <cuda_fp16.h>
#include <cstdint>

#define THREADS 256

// prep-built W1^T fp16 image (hi only), XOR-swizzled rows of 128B
__device__ __align__(16) uint8_t g_B1[32768];
// prep-built W2 mma B-frag pair image: u32[128 k2][8 n], hi @0, lo @4096
__device__ __align__(16) uint8_t g_W2[8192];

// smem byte offsets (no aliasing needed)
#define A_OFF      0        // feat fp16 [256][72], stride 144
#define B1H_OFF    36864    // 32768 (swizzled 128B rows)
#define W2F_OFF    69632    // u32 [128][8] hi, +4096 lo
#define B1V_OFF    77824    // 256 f32
#define B2V_OFF    78848    // 8 f32
#define SMEM_BYTES 78880

#define LDMX4(r, a) asm volatile( \
    "ldmatrix.sync.aligned.m8n8.x4.shared.b16 {%0,%1,%2,%3}, [%4];" \
    : "=r"((r)[0]), "=r"((r)[1]), "=r"((r)[2]), "=r"((r)[3]) : "r"(a))

static __device__ __forceinline__ uint32_t smem_u32(const void* p) {
    uint32_t a;
    asm("{ .reg .u64 t; cvta.to.shared.u64 t, %1; cvt.u32.u64 %0, t; }" : "=r"(a) : "l"(p));
    return a;
}
static __device__ __forceinline__ void mma16816(float* c, const uint32_t* a,
                                                uint32_t b0, uint32_t b1) {
    asm("mma.sync.aligned.m16n8k16.row.col.f32.f16.f16.f32 "
        "{%0,%1,%2,%3}, {%4,%5,%6,%7}, {%8,%9}, {%0,%1,%2,%3};"
        : "+f"(c[0]), "+f"(c[1]), "+f"(c[2]), "+f"(c[3])
        : "r"(a[0]), "r"(a[1]), "r"(a[2]), "r"(a[3]), "r"(b0), "r"(b1));
}
static __device__ __forceinline__ uint32_t packh2(float x, float y) {
    uint32_t r;
    asm("cvt.rn.f16x2.f32 %0, %1, %2;" : "=r"(r) : "f"(y), "f"(x));
    return r;
}
// silu via single-MUFU tanh: x*sigmoid(x) = 0.5x + 0.5x*tanh(x/2)
static __device__ __forceinline__ float silu_f(float x) {
    float hx = 0.5f * x, t;
    asm("tanh.approx.f32 %0, %1;" : "=f"(t) : "f"(hx));
    return fmaf(hx, t, hx);
}

__global__ void prep_kernel(const float* __restrict__ W1, const float* __restrict__ W2) {
    int t0 = blockIdx.x * blockDim.x + threadIdx.x;
    int stride = gridDim.x * blockDim.x;
    for (int idx = t0; idx < 64 * 256; idx += stride) {
        int k = idx >> 8, n = idx & 255;          // W1 is (64,256): W1[k][n]
        __half h = __float2half_rn(W1[idx]);
        uint32_t off = (uint32_t)(n * 128 + (((k >> 3) ^ (n & 7)) << 4) + (k & 7) * 2);
        *(uint16_t*)(g_B1 + off) = *(uint16_t*)&h;
    }
    for (int idx = t0; idx < 1024; idx += stride) {
        int k2 = idx >> 3, n = idx & 7;           // W2 is (256,8)
        float v0 = W2[(2 * k2) * 8 + n], v1 = W2[(2 * k2 + 1) * 8 + n];
        __half h0 = __float2half_rn(v0), h1 = __float2half_rn(v1);
        __half l0 = __float2half_rn(v0 - __half2float(h0));
        __half l1 = __float2half_rn(v1 - __half2float(h1));
        ((uint32_t*)g_W2)[idx] =
            (uint32_t)*(uint16_t*)&h0 | ((uint32_t)*(uint16_t*)&h1 << 16);
        ((uint32_t*)(g_W2 + 4096))[idx] =
            (uint32_t)*(uint16_t*)&l0 | ((uint32_t)*(uint16_t*)&l1 << 16);
    }
}

__global__ void __launch_bounds__(THREADS, 2)
relfeat_mma(const float* __restrict__ Q, const float* __restrict__ K,
            const float* __restrict__ b1, const float* __restrict__ b2,
            float* __restrict__ out) {
    extern __shared__ char sm[];
    const uint32_t smb = smem_u32(sm);
    const int t = threadIdx.x;
    const int w = t >> 5, lane = t & 31;
    const int g = lane >> 2, tq = lane & 3;
    const int bx = blockIdx.x;                 // 0..2047
    const int i = bx & 255, b = bx >> 8;

    // ---- stage weights ----
    {
        const uint4* s1 = (const uint4*)g_B1;
        uint4* d1 = (uint4*)(sm + B1H_OFF);
        for (int idx = t; idx < 2048; idx += THREADS) d1[idx] = s1[idx];
        const uint4* s2 = (const uint4*)g_W2;
        uint4* d2 = (uint4*)(sm + W2F_OFF);
        for (int idx = t; idx < 512; idx += THREADS) d2[idx] = s2[idx];
        ((float*)(sm + B1V_OFF))[t] = b1[t];
        if (t < 8) ((float*)(sm + B2V_OFF))[t] = b2[t];
    }

    // ---- features: thread t computes full 64-vector for row j = t ----
    {
        const float* qr = Q + ((size_t)b * 256 + i) * 10;
        const float* kr = K + ((size_t)b * 256 + t) * 10;
        float qpx = qr[3], qpy = qr[4], qvx = qr[5], qvy = qr[6];
        float dpx = kr[3] - qpx, dpy = kr[4] - qpy;
        float dvx = kr[5] - qvx, dvy = kr[6] - qvy;
        float dist = sqrtf(dpx * dpx + dpy * dpy + 1e-6f);
        float inv_dist = 1.0f / (dist + 0.1f);
        float binv = 1.0f / (dist + 1e-6f);
        float bxn = dpx * binv, byn = dpy * binv;
        float ata = bxn * qr[7] + byn * qr[8];
        float aspect = bxn * kr[7] + byn * kr[8];
        float dot = dpx * dvx + dpy * dvy;
        float ss = dvx * dvx + dvy * dvy;
        float ttca = tanhf(fmaxf(-dot / (ss + 1e-6f), 0.0f));
        float same = (qr[0] == kr[0]) ? 1.0f : 0.0f;
        float dspd = sqrtf(kr[5] * kr[5] + kr[6] * kr[6]) -
                     sqrtf(qvx * qvx + qvy * qvy);

        float f[64];
        const float in4[4] = { dist, inv_dist, ata, aspect };
        #pragma unroll
        for (int d = 0; d < 4; ++d)
            #pragma unroll
            for (int kk = 0; kk < 4; ++kk) {
                float s, c;
                __sincosf(in4[d] * (float)(1 << kk), &s, &c);
                f[d * 8 + kk] = s; f[d * 8 + 4 + kk] = c;
            }
        const float in2[8] = { dpx, dpy, dvx, dvy, ttca, dist, same, dspd };
        #pragma unroll
        for (int d = 0; d < 8; ++d)
            #pragma unroll
            for (int kk = 0; kk < 2; ++kk) {
                float s, c;
                __sincosf(in2[d] * (float)(1 << kk), &s, &c);
                f[32 + d * 4 + kk] = s; f[32 + d * 4 + 2 + kk] = c;
            }
        #pragma unroll
        for (int q = 0; q < 8; ++q) {
            uint32_t h0 = packh2(f[8 * q],     f[8 * q + 1]);
            uint32_t h1 = packh2(f[8 * q + 2], f[8 * q + 3]);
            uint32_t h2 = packh2(f[8 * q + 4], f[8 * q + 5]);
            uint32_t h3 = packh2(f[8 * q + 6], f[8 * q + 7]);
            *(uint4*)(sm + A_OFF + (uint32_t)(t * 144 + q * 16)) =
                make_uint4(h0, h1, h2, h3);
        }
    }
    __syncthreads();

    // ---- A fragments: warp w owns rows w*32..w*32+31 (2 m-tiles) ----
    uint32_t ah[2][4][4];
    #pragma unroll
    for (int mt = 0; mt < 2; ++mt)
        #pragma unroll
        for (int s = 0; s < 4; ++s) {
            uint32_t row = (uint32_t)(w * 32 + mt * 16 + (lane & 15));
            uint32_t addr = smb + A_OFF + row * 144 + 32 * s + ((lane >> 4) & 1) * 16;
            LDMX4(ah[mt][s], addr);
        }

    const float* b1v = (const float*)(sm + B1V_OFF);
    const float* b2v = (const float*)(sm + B2V_OFF);
    const uint32_t* w2h = (const uint32_t*)(sm + W2F_OFF);
    const uint32_t* w2l = (const uint32_t*)(sm + W2F_OFF + 4096);

    float o[2][4];
    #pragma unroll
    for (int mt = 0; mt < 2; ++mt) {
        o[mt][0] = b2v[2 * tq]; o[mt][1] = b2v[2 * tq + 1];
        o[mt][2] = o[mt][0];    o[mt][3] = o[mt][1];
    }

    #pragma unroll 1
    for (int cch = 0; cch < 4; ++cch) {
        #pragma unroll
        for (int half = 0; half < 2; ++half) {
            const int nbase = cch * 64 + half * 32;
            // ---- GEMM1: n-range [nbase, nbase+32), both m-tiles ----
            float acc[2][4][4];
            #pragma unroll
            for (int nt = 0; nt < 4; ++nt) {
                const float2 bb = *(const float2*)(b1v + nbase + nt * 8 + 2 * tq);
                #pragma unroll
                for (int mt = 0; mt < 2; ++mt) {
                    acc[mt][nt][0] = bb.x; acc[mt][nt][1] = bb.y;
                    acc[mt][nt][2] = bb.x; acc[mt][nt][3] = bb.y;
                }
            }
            #pragma unroll
            for (int s2m = 0; s2m < 2; ++s2m)
                #pragma unroll
                for (int nt = 0; nt < 4; ++nt) {
                    uint32_t brow = (uint32_t)(nbase + nt * 8 + (lane & 7));
                    uint32_t c16 = (uint32_t)(4 * s2m + (lane >> 3));
                    uint32_t baddr = smb + B1H_OFF + brow * 128 +
                                     ((c16 ^ (brow & 7)) << 4);
                    uint32_t bh[4];
                    LDMX4(bh, baddr);
                    const int s = 2 * s2m;
                    #pragma unroll
                    for (int mt = 0; mt < 2; ++mt) {
                        mma16816(acc[mt][nt], ah[mt][s],     bh[0], bh[1]);
                        mma16816(acc[mt][nt], ah[mt][s + 1], bh[2], bh[3]);
                    }
                }
            // ---- silu + GEMM2 for this half (k = nbase..nbase+32) ----
            #pragma unroll
            for (int s2 = 0; s2 < 2; ++s2) {
                const int s2g = half * 2 + s2;
                const int kw = (cch * 32 + 8 * s2g + tq) * 8 + g;
                const uint32_t b0h = w2h[kw], b1h = w2h[kw + 32];
                const uint32_t b0l = w2l[kw], b1l = w2l[kw + 32];
                #pragma unroll
                for (int mt = 0; mt < 2; ++mt) {
                    uint32_t a2[4];
                    a2[0] = packh2(silu_f(acc[mt][2 * s2][0]),
                                   silu_f(acc[mt][2 * s2][1]));
                    a2[1] = packh2(silu_f(acc[mt][2 * s2][2]),
                                   silu_f(acc[mt][2 * s2][3]));
                    a2[2] = packh2(silu_f(acc[mt][2 * s2 + 1][0]),
                                   silu_f(acc[mt][2 * s2 + 1][1]));
                    a2[3] = packh2(silu_f(acc[mt][2 * s2 + 1][2]),
                                   silu_f(acc[mt][2 * s2 + 1][3]));
                    mma16816(o[mt], a2, b0h, b1h);
                    mma16816(o[mt], a2, b0l, b1l);
                }
            }
        }
    }

    // ---- store out[b,h,i,j]: rows w*32+mt*16+g (+8); heads 2tq, 2tq+1 ----
    #pragma unroll
    for (int mt = 0; mt < 2; ++mt) {
        const int j0 = w * 32 + mt * 16 + g;
        const size_t p0 = (((size_t)(b * 8 + 2 * tq)) * 256 + i) * 256 + j0;
        const size_t p1 = (((size_t)(b * 8 + 2 * tq + 1)) * 256 + i) * 256 + j0;
        out[p0]     = o[mt][0];
        out[p1]     = o[mt][1];
        out[p0 + 8] = o[mt][2];
        out[p1 + 8] = o[mt][3];
    }
}

extern "C" void kernel_launch(void* const* d_in, const int* in_sizes, int n_in,
                              void* d_out, int out_size) {
    const float* Q  = (const float*)d_in[0];
    const float* K  = (const float*)d_in[1];
    const float* W1 = (const float*)d_in[2];
    const float* b1 = (const float*)d_in[3];
    const float* W2 = (const float*)d_in[4];
    const float* b2 = (const float*)d_in[5];
    float* out = (float*)d_out;

    prep_kernel<<<16, THREADS>>>(W1, W2);
    cudaFuncSetAttribute(relfeat_mma, cudaFuncAttributeMaxDynamicSharedMemorySize,
                         SMEM_BYTES);
    relfeat_mma<<<2048, THREADS, SMEM_BYTES>>>(Q, K, b1, b2, out);
}

// round 11
// speedup vs baseline: 8.2943x; 1.0767x over previous
#include <cuda_runtime.h>
#include <cuda_fp16.h>
#include <cstdint>

#define THREADS 256

// prep-built W1^T fp16 image (hi only), XOR-swizzled rows of 128B
__device__ __align__(16) uint8_t g_B1[32768];
// prep-built W2 mma B-frag image (hi only): u32[128 k2][8 n]
__device__ __align__(16) uint8_t g_W2[4096];

// smem byte offsets
#define A_OFF      0        // feat fp16 [256][72], stride 144
#define B1H_OFF    36864    // 32768 (swizzled 128B rows)
#define W2F_OFF    69632    // u32 [128][8]
#define B1V_OFF    73728    // 256 f32
#define B2V_OFF    74752    // 8 f32
#define SMEM_BYTES 74784

#define LDMX4(r, a) asm volatile( \
    "ldmatrix.sync.aligned.m8n8.x4.shared.b16 {%0,%1,%2,%3}, [%4];" \
    : "=r"((r)[0]), "=r"((r)[1]), "=r"((r)[2]), "=r"((r)[3]) : "r"(a))

static __device__ __forceinline__ uint32_t smem_u32(const void* p) {
    uint32_t a;
    asm("{ .reg .u64 t; cvta.to.shared.u64 t, %1; cvt.u32.u64 %0, t; }" : "=r"(a) : "l"(p));
    return a;
}
static __device__ __forceinline__ void mma16816(float* c, const uint32_t* a,
                                                uint32_t b0, uint32_t b1) {
    asm("mma.sync.aligned.m16n8k16.row.col.f32.f16.f16.f32 "
        "{%0,%1,%2,%3}, {%4,%5,%6,%7}, {%8,%9}, {%0,%1,%2,%3};"
        : "+f"(c[0]), "+f"(c[1]), "+f"(c[2]), "+f"(c[3])
        : "r"(a[0]), "r"(a[1]), "r"(a[2]), "r"(a[3]), "r"(b0), "r"(b1));
}
static __device__ __forceinline__ uint32_t packh2(float x, float y) {
    uint32_t r;
    asm("cvt.rn.f16x2.f32 %0, %1, %2;" : "=r"(r) : "f"(y), "f"(x));
    return r;
}
// silu via tanh.approx: x*sigmoid(x) = 0.5x + 0.5x*tanh(x/2)
static __device__ __forceinline__ float silu_f(float x) {
    float hx = 0.5f * x, t;
    asm("tanh.approx.f32 %0, %1;" : "=f"(t) : "f"(hx));
    return fmaf(hx, t, hx);
}

__global__ void prep_kernel(const float* __restrict__ W1, const float* __restrict__ W2) {
    int t0 = blockIdx.x * blockDim.x + threadIdx.x;
    int stride = gridDim.x * blockDim.x;
    for (int idx = t0; idx < 64 * 256; idx += stride) {
        int k = idx >> 8, n = idx & 255;          // W1 is (64,256): W1[k][n]
        __half h = __float2half_rn(W1[idx]);
        uint32_t off = (uint32_t)(n * 128 + (((k >> 3) ^ (n & 7)) << 4) + (k & 7) * 2);
        *(uint16_t*)(g_B1 + off) = *(uint16_t*)&h;
    }
    for (int idx = t0; idx < 1024; idx += stride) {
        int k2 = idx >> 3, n = idx & 7;           // W2 is (256,8)
        __half h0 = __float2half_rn(W2[(2 * k2) * 8 + n]);
        __half h1 = __float2half_rn(W2[(2 * k2 + 1) * 8 + n]);
        ((uint32_t*)g_W2)[idx] =
            (uint32_t)*(uint16_t*)&h0 | ((uint32_t)*(uint16_t*)&h1 << 16);
    }
}

__global__ void __launch_bounds__(THREADS, 2)
relfeat_mma(const float* __restrict__ Q, const float* __restrict__ K,
            const float* __restrict__ b1, const float* __restrict__ b2,
            float* __restrict__ out) {
    extern __shared__ char sm[];
    const uint32_t smb = smem_u32(sm);
    const int t = threadIdx.x;
    const int w = t >> 5, lane = t & 31;
    const int g = lane >> 2, tq = lane & 3;
    const int bx = blockIdx.x;                 // 0..2047
    const int i = bx & 255, b = bx >> 8;

    // ---- stage weights ----
    {
        const uint4* s1 = (const uint4*)g_B1;
        uint4* d1 = (uint4*)(sm + B1H_OFF);
        for (int idx = t; idx < 2048; idx += THREADS) d1[idx] = s1[idx];
        const uint4* s2 = (const uint4*)g_W2;
        uint4* d2 = (uint4*)(sm + W2F_OFF);
        for (int idx = t; idx < 256; idx += THREADS) d2[idx] = s2[idx];
        ((float*)(sm + B1V_OFF))[t] = b1[t];
        if (t < 8) ((float*)(sm + B2V_OFF))[t] = b2[t];
    }

    // ---- features: thread t computes full 64-vector for row j = t ----
    {
        const float* qr = Q + ((size_t)b * 256 + i) * 10;
        const float* kr = K + ((size_t)b * 256 + t) * 10;
        float qpx = qr[3], qpy = qr[4], qvx = qr[5], qvy = qr[6];
        float dpx = kr[3] - qpx, dpy = kr[4] - qpy;
        float dvx = kr[5] - qvx, dvy = kr[6] - qvy;
        float dist = sqrtf(dpx * dpx + dpy * dpy + 1e-6f);
        float inv_dist = 1.0f / (dist + 0.1f);
        float binv = 1.0f / (dist + 1e-6f);
        float bxn = dpx * binv, byn = dpy * binv;
        float ata = bxn * qr[7] + byn * qr[8];
        float aspect = bxn * kr[7] + byn * kr[8];
        float dot = dpx * dvx + dpy * dvy;
        float ss = dvx * dvx + dvy * dvy;
        float ttca = tanhf(fmaxf(-dot / (ss + 1e-6f), 0.0f));
        float same = (qr[0] == kr[0]) ? 1.0f : 0.0f;
        float dspd = sqrtf(kr[5] * kr[5] + kr[6] * kr[6]) -
                     sqrtf(qvx * qvx + qvy * qvy);

        float f[64];
        const float in4[4] = { dist, inv_dist, ata, aspect };
        #pragma unroll
        for (int d = 0; d < 4; ++d)
            #pragma unroll
            for (int kk = 0; kk < 4; ++kk) {
                float s, c;
                __sincosf(in4[d] * (float)(1 << kk), &s, &c);
                f[d * 8 + kk] = s; f[d * 8 + 4 + kk] = c;
            }
        const float in2[8] = { dpx, dpy, dvx, dvy, ttca, dist, same, dspd };
        #pragma unroll
        for (int d = 0; d < 8; ++d)
            #pragma unroll
            for (int kk = 0; kk < 2; ++kk) {
                float s, c;
                __sincosf(in2[d] * (float)(1 << kk), &s, &c);
                f[32 + d * 4 + kk] = s; f[32 + d * 4 + 2 + kk] = c;
            }
        #pragma unroll
        for (int q = 0; q < 8; ++q) {
            uint32_t h0 = packh2(f[8 * q],     f[8 * q + 1]);
            uint32_t h1 = packh2(f[8 * q + 2], f[8 * q + 3]);
            uint32_t h2 = packh2(f[8 * q + 4], f[8 * q + 5]);
            uint32_t h3 = packh2(f[8 * q + 6], f[8 * q + 7]);
            *(uint4*)(sm + A_OFF + (uint32_t)(t * 144 + q * 16)) =
                make_uint4(h0, h1, h2, h3);
        }
    }
    __syncthreads();

    // ---- A fragments: warp w owns rows w*32..w*32+31 (2 m-tiles) ----
    uint32_t ah[2][4][4];
    #pragma unroll
    for (int mt = 0; mt < 2; ++mt)
        #pragma unroll
        for (int s = 0; s < 4; ++s) {
            uint32_t row = (uint32_t)(w * 32 + mt * 16 + (lane & 15));
            uint32_t addr = smb + A_OFF + row * 144 + 32 * s + ((lane >> 4) & 1) * 16;
            LDMX4(ah[mt][s], addr);
        }

    const float* b1v = (const float*)(sm + B1V_OFF);
    const float* b2v = (const float*)(sm + B2V_OFF);
    const uint32_t* w2h = (const uint32_t*)(sm + W2F_OFF);

    float o[2][4];
    #pragma unroll
    for (int mt = 0; mt < 2; ++mt) {
        o[mt][0] = b2v[2 * tq]; o[mt][1] = b2v[2 * tq + 1];
        o[mt][2] = o[mt][0];    o[mt][3] = o[mt][1];
    }

    #pragma unroll 2
    for (int cch = 0; cch < 4; ++cch) {
        #pragma unroll
        for (int half = 0; half < 2; ++half) {
            const int nbase = cch * 64 + half * 32;
            // ---- GEMM1: n-range [nbase, nbase+32), both m-tiles ----
            float acc[2][4][4];
            #pragma unroll
            for (int nt = 0; nt < 4; ++nt) {
                const float2 bb = *(const float2*)(b1v + nbase + nt * 8 + 2 * tq);
                #pragma unroll
                for (int mt = 0; mt < 2; ++mt) {
                    acc[mt][nt][0] = bb.x; acc[mt][nt][1] = bb.y;
                    acc[mt][nt][2] = bb.x; acc[mt][nt][3] = bb.y;
                }
            }
            #pragma unroll
            for (int s2m = 0; s2m < 2; ++s2m)
                #pragma unroll
                for (int nt = 0; nt < 4; ++nt) {
                    uint32_t brow = (uint32_t)(nbase + nt * 8 + (lane & 7));
                    uint32_t c16 = (uint32_t)(4 * s2m + (lane >> 3));
                    uint32_t baddr = smb + B1H_OFF + brow * 128 +
                                     ((c16 ^ (brow & 7)) << 4);
                    uint32_t bh[4];
                    LDMX4(bh, baddr);
                    const int s = 2 * s2m;
                    #pragma unroll
                    for (int mt = 0; mt < 2; ++mt) {
                        mma16816(acc[mt][nt], ah[mt][s],     bh[0], bh[1]);
                        mma16816(acc[mt][nt], ah[mt][s + 1], bh[2], bh[3]);
                    }
                }
            // ---- silu + GEMM2 (W2 hi only) ----
            #pragma unroll
            for (int s2 = 0; s2 < 2; ++s2) {
                const int s2g = half * 2 + s2;
                const int kw = (cch * 32 + 8 * s2g + tq) * 8 + g;
                const uint32_t b0h = w2h[kw], b1h = w2h[kw + 32];
                #pragma unroll
                for (int mt = 0; mt < 2; ++mt) {
                    uint32_t a2[4];
                    a2[0] = packh2(silu_f(acc[mt][2 * s2][0]),
                                   silu_f(acc[mt][2 * s2][1]));
                    a2[1] = packh2(silu_f(acc[mt][2 * s2][2]),
                                   silu_f(acc[mt][2 * s2][3]));
                    a2[2] = packh2(silu_f(acc[mt][2 * s2 + 1][0]),
                                   silu_f(acc[mt][2 * s2 + 1][1]));
                    a2[3] = packh2(silu_f(acc[mt][2 * s2 + 1][2]),
                                   silu_f(acc[mt][2 * s2 + 1][3]));
                    mma16816(o[mt], a2, b0h, b1h);
                }
            }
        }
    }

    // ---- store out[b,h,i,j]: rows w*32+mt*16+g (+8); heads 2tq, 2tq+1 ----
    #pragma unroll
    for (int mt = 0; mt < 2; ++mt) {
        const int j0 = w * 32 + mt * 16 + g;
        const size_t p0 = (((size_t)(b * 8 + 2 * tq)) * 256 + i) * 256 + j0;
        const size_t p1 = (((size_t)(b * 8 + 2 * tq + 1)) * 256 + i) * 256 + j0;
        out[p0]     = o[mt][0];
        out[p1]     = o[mt][1];
        out[p0 + 8] = o[mt][2];
        out[p1 + 8] = o[mt][3];
    }
}

extern "C" void kernel_launch(void* const* d_in, const int* in_sizes, int n_in,
                              void* d_out, int out_size) {
    const float* Q  = (const float*)d_in[0];
    const float* K  = (const float*)d_in[1];
    const float* W1 = (const float*)d_in[2];
    const float* b1 = (const float*)d_in[3];
    const float* W2 = (const float*)d_in[4];
    const float* b2 = (const float*)d_in[5];
    float* out = (float*)d_out;

    prep_kernel<<<16, THREADS>>>(W1, W2);
    cudaFuncSetAttribute(relfeat_mma, cudaFuncAttributeMaxDynamicSharedMemorySize,
                         SMEM_BYTES);
    relfeat_mma<<<2048, THREADS, SMEM_BYTES>>>(Q, K, b1, b2, out);
}